// round 2
// baseline (speedup 1.0000x reference)
#include <cuda_runtime.h>
#include <math.h>

#define NN 20000
#define NE 50000
#define HH 128
#define UCNT 256
#define MAXDEG 512
#define DSCALE 0.17677669529663687f   // 1/sqrt(32)

// ---------------- device scratch (static, no allocation) ----------------
__device__ int   g_n2s[NN];
__device__ unsigned char g_nneed[NN];
__device__ unsigned char g_eneed[NE];
__device__ int   g_deg[UCNT];
__device__ int   g_eidx[UCNT * MAXDEG];
__device__ int   g_nbr[UCNT * MAXDEG];
__device__ int   g_Lcnt, g_Ecnt;
__device__ int   g_Llist[NN], g_nodeL[NN];
__device__ int   g_Elist[NE], g_eE[NE];
__device__ int   g_tgtL[UCNT], g_canon[UCNT], g_hasnbr[UCNT];
__device__ int   g_rowSlot[NN];

__device__ float g_xL[NN * HH];
__device__ float g_tfL[NN * HH];
__device__ float g_Ak[NN * HH];
__device__ float g_Av[NN * HH];
__device__ float g_tfe1[NE * HH];
__device__ float g_tfe[NE * HH];
__device__ float g_Bk[NE * HH];
__device__ float g_Bv[NE * HH];
__device__ float g_q[UCNT * HH];
__device__ float g_o[UCNT * HH];
__device__ float g_attn[UCNT * HH];
__device__ float g_aggin[UCNT * HH];
__device__ float g_agg[UCNT * HH];
__device__ float g_e1[UCNT * HH];
__device__ float g_emb[UCNT * 64];
__device__ float g_pair[128 * 128];
__device__ float g_z1[128 * 128];
__device__ float g_z2[128 * 64];

// transposed weights
#define WT_TOTAL 294912
__device__ float g_Wt[WT_TOTAL];

__constant__ int c_moutD[19] = {128,128,128,128,128,128,128,128,128,
                                128,128,128,128,128,128,128, 64,128, 64};
__constant__ int c_moff[19]  = {0,16384,32768,49152,65536,81920,98304,114688,
                                131072,147456,163840,180224,196608,212992,
                                229376,245760,262144,270336,286720};

static const int h_moff[19]  = {0,16384,32768,49152,65536,81920,98304,114688,
                                131072,147456,163840,180224,196608,212992,
                                229376,245760,262144,270336,286720};

struct WPtrs { const float* p[19]; };

// ---------------- setup kernels ----------------
__global__ void k_init() {
    int i = blockIdx.x * blockDim.x + threadIdx.x;
    if (i < NN) { g_n2s[i] = -1; g_nneed[i] = 0; g_rowSlot[i] = -1; }
    if (i < NE) g_eneed[i] = 0;
    if (i < UCNT) g_deg[i] = 0;
    if (i == 0) { g_Lcnt = 0; g_Ecnt = 0; }
}

__global__ void k_mark(const int* __restrict__ tp) {
    if (threadIdx.x == 0) {
        for (int u = 0; u < UCNT; u++) {
            int t = tp[u];
            g_n2s[t] = u;     // last write wins -> deterministic canonical slot
            g_nneed[t] = 1;
        }
    }
}

__global__ void k_scan(const int* __restrict__ src, const int* __restrict__ dst) {
    int i = blockIdx.x * blockDim.x + threadIdx.x;
    if (i >= NE) return;
    int s = src[i], d = dst[i];
    int su = g_n2s[s];
    if (su >= 0) {
        int j = atomicAdd(&g_deg[su], 1);
        if (j < MAXDEG) { g_eidx[su * MAXDEG + j] = i; g_nbr[su * MAXDEG + j] = d; }
        g_eneed[i] = 1; g_nneed[d] = 1;
    }
    int du = g_n2s[d];
    if (du >= 0 && d != s) {
        int j = atomicAdd(&g_deg[du], 1);
        if (j < MAXDEG) { g_eidx[du * MAXDEG + j] = i; g_nbr[du * MAXDEG + j] = s; }
        g_eneed[i] = 1; g_nneed[s] = 1;
    }
}

__global__ void k_sort() {
    int u = threadIdx.x;
    if (u >= UCNT) return;
    int dg = g_deg[u]; if (dg > MAXDEG) dg = MAXDEG; g_deg[u] = dg;
    int* ei = g_eidx + u * MAXDEG;
    int* nb = g_nbr + u * MAXDEG;
    for (int i = 1; i < dg; i++) {
        int ke = ei[i], kn = nb[i], j = i - 1;
        while (j >= 0 && ei[j] > ke) { ei[j+1] = ei[j]; nb[j+1] = nb[j]; j--; }
        ei[j+1] = ke; nb[j+1] = kn;
    }
}

__global__ void k_compactN() {
    int n = blockIdx.x * blockDim.x + threadIdx.x;
    if (n < NN && g_nneed[n]) {
        int i = atomicAdd(&g_Lcnt, 1);
        g_Llist[i] = n; g_nodeL[n] = i;
    }
}

__global__ void k_compactE() {
    int e = blockIdx.x * blockDim.x + threadIdx.x;
    if (e < NE && g_eneed[e]) {
        int i = atomicAdd(&g_Ecnt, 1);
        g_Elist[i] = e; g_eE[e] = i;
    }
}

__global__ void k_finalize(const int* __restrict__ tp) {
    int u = threadIdx.x;
    if (u < UCNT) {
        int t = tp[u];
        g_tgtL[u] = g_nodeL[t];
        int c = g_n2s[t];
        g_canon[u] = c;
        g_hasnbr[u] = (g_deg[c] > 0) ? 1 : 0;
    }
    __syncthreads();
    if (u == 0) {
        for (int v = 0; v < UCNT; v++)
            if (g_canon[v] == v) g_rowSlot[g_tgtL[v]] = v;
    }
}

__global__ void k_transpose(WPtrs ws) {
    int m = blockIdx.y;
    int outD = c_moutD[m];
    int total = outD * 128;
    int i = blockIdx.x * blockDim.x + threadIdx.x;
    if (i >= total) return;
    int k = i / outD, j = i - k * outD;
    g_Wt[c_moff[m] + i] = ws.p[m][j * 128 + k];
}

// ---------------- generic row-GEMM (inDim = 128) ----------------
__device__ __forceinline__ float* bufsel(int s) {
    switch (s) {
        case 0:  return g_xL;    case 1:  return g_tfL;  case 2:  return g_Ak;
        case 3:  return g_Av;    case 4:  return g_tfe1; case 5:  return g_tfe;
        case 6:  return g_Bk;    case 7:  return g_Bv;   case 8:  return g_q;
        case 9:  return g_o;     case 10: return g_attn; case 11: return g_aggin;
        case 12: return g_agg;   case 13: return g_e1;   case 14: return g_emb;
        case 15: return g_pair;  case 16: return g_z1;   default: return g_z2;
    }
}

#define RB 4
#define RPB 16

__global__ void __launch_bounds__(128)
k_rowmm(const float* __restrict__ extin, int insel, int gsel,
        int woff, const float* __restrict__ b,
        int outsel, int cntsel, int outD, int doRelu)
{
    const float* in = (insel >= 0) ? (const float*)bufsel(insel) : extin;
    float* out = bufsel(outsel);
    int cnt = (cntsel == 0) ? g_Lcnt : (cntsel == 1) ? g_Ecnt :
              (cntsel == 2) ? UCNT : 128;
    int tid = threadIdx.x, w = tid >> 5, lane = tid & 31;
    __shared__ float s_in[RPB][HH];
    bool act = (lane * 4 < outD);
    int od4 = outD >> 2;
    const float4* wp = (const float4*)(g_Wt + woff) + lane;

    for (int r0 = blockIdx.x * RPB; r0 < cnt; r0 += gridDim.x * RPB) {
        for (int rr = w; rr < RPB; rr += 4) {
            int r = r0 + rr;
            int rc = (r < cnt) ? r : r0;
            int sr = (gsel == 1) ? g_Llist[rc] : (gsel == 2) ? g_tgtL[rc] : rc;
            ((float4*)s_in[rr])[lane] = ((const float4*)(in + (size_t)sr * HH))[lane];
        }
        __syncthreads();

        float acc[RB][4];
#pragma unroll
        for (int r = 0; r < RB; r++)
            acc[r][0] = acc[r][1] = acc[r][2] = acc[r][3] = 0.f;

#pragma unroll 4
        for (int k = 0; k < HH; k++) {
            float4 wv = act ? wp[k * od4] : make_float4(0.f,0.f,0.f,0.f);
#pragma unroll
            for (int r = 0; r < RB; r++) {
                float xv = s_in[w * RB + r][k];
                acc[r][0] = fmaf(xv, wv.x, acc[r][0]);
                acc[r][1] = fmaf(xv, wv.y, acc[r][1]);
                acc[r][2] = fmaf(xv, wv.z, acc[r][2]);
                acc[r][3] = fmaf(xv, wv.w, acc[r][3]);
            }
        }
        float4 bv = (b != nullptr && act) ? ((const float4*)b)[lane]
                                          : make_float4(0.f,0.f,0.f,0.f);
#pragma unroll
        for (int r = 0; r < RB; r++) {
            int row = r0 + w * RB + r;
            if (row < cnt && act) {
                float o0 = acc[r][0]+bv.x, o1 = acc[r][1]+bv.y;
                float o2 = acc[r][2]+bv.z, o3 = acc[r][3]+bv.w;
                if (doRelu) {
                    o0 = fmaxf(o0,0.f); o1 = fmaxf(o1,0.f);
                    o2 = fmaxf(o2,0.f); o3 = fmaxf(o3,0.f);
                }
                ((float4*)(out + (size_t)row * outD))[lane] =
                    make_float4(o0,o1,o2,o3);
            }
        }
        __syncthreads();
    }
}

// ---------------- time-encoder stage 1 ----------------
__global__ void k_tfe1(const float* __restrict__ ts,
                       const float* __restrict__ W1, const float* __restrict__ b1) {
    int total = g_Ecnt * HH;
    for (int idx = blockIdx.x * blockDim.x + threadIdx.x; idx < total;
         idx += gridDim.x * blockDim.x) {
        int j = idx >> 7, t = idx & 127;
        float tv = ts[g_Elist[j]];
        g_tfe1[idx] = fmaxf(fmaf(tv, W1[t], b1[t]), 0.f);
    }
}

// ---------------- attention: block per slot, warp per head ----------------
__global__ void __launch_bounds__(128) k_attn() {
    int u = blockIdx.x;
    int cu = g_canon[u];
    int dg = g_deg[cu];
    __shared__ int   sRow[MAXDEG];
    __shared__ int   sJe[MAXDEG];
    __shared__ float sSc[4][MAXDEG];
    int tid = threadIdx.x;
    for (int j = tid; j < dg; j += 128) {
        sRow[j] = g_nodeL[g_nbr[cu * MAXDEG + j]];
        sJe[j]  = g_eE[g_eidx[cu * MAXDEG + j]];
    }
    __syncthreads();
    int hh = tid >> 5, lane = tid & 31;
    int off = hh * 32 + lane;
    float qv = g_q[u * HH + off];

    for (int j = 0; j < dg; j++) {
        int rA = sRow[j] * HH + off;
        int rB = sJe[j] * HH + off;
        float t = qv * (g_Ak[rA] + g_Bk[rB]);
#pragma unroll
        for (int m = 16; m > 0; m >>= 1) t += __shfl_xor_sync(0xffffffffu, t, m);
        if (lane == 0) sSc[hh][j] = t * DSCALE;
    }
    __syncwarp();
    float mx = -1e30f;
    for (int j = lane; j < dg; j += 32) mx = fmaxf(mx, sSc[hh][j]);
#pragma unroll
    for (int m = 16; m > 0; m >>= 1) mx = fmaxf(mx, __shfl_xor_sync(0xffffffffu, mx, m));
    float sm = 0.f;
    for (int j = lane; j < dg; j += 32) {
        float p = expf(sSc[hh][j] - mx);
        sSc[hh][j] = p;
        sm += p;
    }
#pragma unroll
    for (int m = 16; m > 0; m >>= 1) sm += __shfl_xor_sync(0xffffffffu, sm, m);
    __syncwarp();
    float inv = (dg > 0) ? (1.f / sm) : 0.f;
    float acc = 0.f;
    for (int j = 0; j < dg; j++) {
        int rA = sRow[j] * HH + off;
        int rB = sJe[j] * HH + off;
        acc = fmaf(sSc[hh][j] * inv, g_Av[rA] + g_Bv[rB], acc);
    }
    g_o[u * HH + off] = acc;
}

// ---------------- misc small kernels ----------------
__global__ void k_sel() {
    int idx = blockIdx.x * blockDim.x + threadIdx.x;
    if (idx >= UCNT * HH) return;
    int u = idx >> 7, i = idx & 127;
    g_aggin[idx] = g_hasnbr[u] ? g_attn[idx] : g_tfL[g_tgtL[u] * HH + i];
}

__global__ void k_postlayer() {
    int total = g_Lcnt * HH;
    for (int idx = blockIdx.x * blockDim.x + threadIdx.x; idx < total;
         idx += gridDim.x * blockDim.x) {
        int r = idx >> 7, i = idx & 127;
        int s = g_rowSlot[r];
        float v = (s >= 0) ? g_agg[s * HH + i] : g_xL[idx];
        g_xL[idx] = fmaxf(v, 0.f);
    }
}

__global__ void k_pair() {
    int idx = blockIdx.x * blockDim.x + threadIdx.x;
    if (idx >= 128 * 128) return;
    int p = idx >> 7, i = idx & 127;
    g_pair[idx] = (i < 64) ? g_emb[(2*p)*64 + i] : g_emb[(2*p+1)*64 + (i-64)];
}

__global__ void k_lp3(const float* __restrict__ W, const float* __restrict__ b,
                      float* __restrict__ out) {
    int gid = blockIdx.x * blockDim.x + threadIdx.x;
    int p = gid >> 5, lane = gid & 31;
    if (p >= 128) return;
    float a = g_z2[p*64 + lane] * W[lane] + g_z2[p*64 + 32 + lane] * W[32 + lane];
#pragma unroll
    for (int m = 16; m > 0; m >>= 1) a += __shfl_xor_sync(0xffffffffu, a, m);
    if (lane == 0) out[p] = 1.f / (1.f + expf(-(a + b[0])));
}

// ---------------- launch ----------------
extern "C" void kernel_launch(void* const* d_in, const int* in_sizes, int n_in,
                              void* d_out, int out_size) {
    const float* nf   = (const float*)d_in[0];
    const int*   eidx = (const int*)d_in[1];
    const float* ets  = (const float*)d_in[2];
    const int*   tp   = (const int*)d_in[3];
    const float* in_W = (const float*)d_in[4];
    const float* in_b = (const float*)d_in[5];
    const float* teW1 = (const float*)d_in[6];
    const float* teB1 = (const float*)d_in[7];
    const float* teW2 = (const float*)d_in[8];
    const float* teB2 = (const float*)d_in[9];
    const float* aiW  = (const float*)d_in[10];
    const float* aiB  = (const float*)d_in[11];
    const float* aoW  = (const float*)d_in[12];
    const float* aoB  = (const float*)d_in[13];
    const float* ftW  = (const float*)d_in[14];
    const float* ftB  = (const float*)d_in[15];
    const float* opW  = (const float*)d_in[16];
    const float* opB  = (const float*)d_in[17];
    const float* o1W  = (const float*)d_in[18];
    const float* o1B  = (const float*)d_in[19];
    const float* o2W  = (const float*)d_in[20];
    const float* o2B  = (const float*)d_in[21];
    const float* l1W  = (const float*)d_in[22];
    const float* l1B  = (const float*)d_in[23];
    const float* l2W  = (const float*)d_in[24];
    const float* l2B  = (const float*)d_in[25];
    const float* l3W  = (const float*)d_in[26];
    const float* l3B  = (const float*)d_in[27];
    float* out = (float*)d_out;

    const int* src = eidx;
    const int* dst = eidx + NE;

    // setup
    k_init<<<(NE + 255) / 256, 256>>>();
    k_mark<<<1, 32>>>(tp);
    k_scan<<<(NE + 255) / 256, 256>>>(src, dst);
    k_sort<<<1, 256>>>();
    k_compactN<<<(NN + 255) / 256, 256>>>();
    k_compactE<<<(NE + 255) / 256, 256>>>();
    k_finalize<<<1, 256>>>(tp);

    WPtrs ws;
    ws.p[0] = in_W;
    for (int l = 0; l < 2; l++) {
        ws.p[1 + 7*l] = ftW + l * 16384;
        ws.p[2 + 7*l] = teW2 + l * 16384;
        ws.p[3 + 7*l] = aiW + l * 384 * 128;            // Wq
        ws.p[4 + 7*l] = aiW + l * 384 * 128 + 16384;    // Wk
        ws.p[5 + 7*l] = aiW + l * 384 * 128 + 32768;    // Wv
        ws.p[6 + 7*l] = aoW + l * 16384;
        ws.p[7 + 7*l] = opW + l * 16384;
    }
    ws.p[15] = o1W; ws.p[16] = o2W; ws.p[17] = l1W; ws.p[18] = l2W;
    {
        dim3 g((16384 + 255) / 256, 19);
        k_transpose<<<g, 256>>>(ws);
    }

    const int GMM = 120;
    // x = nf[Llist] @ in_W.T + in_b
    k_rowmm<<<GMM, 128>>>(nf, -1, 1, h_moff[0], in_b, 0, 0, 128, 0);

    for (int l = 0; l < 2; l++) {
        int mft = 1 + 7*l, mte = 2 + 7*l, mq = 3 + 7*l, mk = 4 + 7*l,
            mv = 5 + 7*l, mao = 6 + 7*l, mop = 7 + 7*l;
        const float* bq = aiB + l * 384;
        const float* bk = bq + 128;
        const float* bv = bq + 256;

        k_rowmm<<<GMM, 128>>>(nullptr, 0, 0, h_moff[mft], ftB + l*128, 1, 0, 128, 0); // tf
        k_rowmm<<<GMM, 128>>>(nullptr, 1, 0, h_moff[mk], nullptr, 2, 0, 128, 0);      // Ak
        k_rowmm<<<GMM, 128>>>(nullptr, 1, 0, h_moff[mv], nullptr, 3, 0, 128, 0);      // Av
        k_tfe1<<<256, 256>>>(ets, teW1 + l*128, teB1 + l*128);
        k_rowmm<<<GMM, 128>>>(nullptr, 4, 0, h_moff[mte], teB2 + l*128, 5, 1, 128, 0);// tfe
        k_rowmm<<<GMM, 128>>>(nullptr, 5, 0, h_moff[mk], bk, 6, 1, 128, 0);           // Bk
        k_rowmm<<<GMM, 128>>>(nullptr, 5, 0, h_moff[mv], bv, 7, 1, 128, 0);           // Bv
        k_rowmm<<<16, 128>>>(nullptr, 1, 2, h_moff[mq], bq, 8, 2, 128, 0);            // q
        k_attn<<<UCNT, 128>>>();
        k_rowmm<<<16, 128>>>(nullptr, 9, 0, h_moff[mao], aoB + l*128, 10, 2, 128, 0); // attn
        k_sel<<<(UCNT*HH + 255)/256, 256>>>();
        k_rowmm<<<16, 128>>>(nullptr, 11, 0, h_moff[mop], opB + l*128, 12, 2, 128, 0);// agg
        k_postlayer<<<256, 256>>>();
    }

    k_rowmm<<<16, 128>>>(nullptr, 0, 2, h_moff[15], o1B, 13, 2, 128, 1);  // e1 (relu)
    k_rowmm<<<16, 128>>>(nullptr, 13, 0, h_moff[16], o2B, 14, 2, 64, 0);  // emb
    k_pair<<<(128*128 + 255)/256, 256>>>();
    k_rowmm<<<8, 128>>>(nullptr, 15, 0, h_moff[17], l1B, 16, 3, 128, 1);  // z1
    k_rowmm<<<8, 128>>>(nullptr, 16, 0, h_moff[18], l2B, 17, 3, 64, 1);   // z2
    k_lp3<<<32, 128>>>(l3W, l3B, out);
}

// round 3
// speedup vs baseline: 2.2996x; 2.2996x over previous
#include <cuda_runtime.h>
#include <math.h>

#define NN 20000
#define NE 50000
#define HH 128
#define UCNT 256
#define MAXDEG 512
#define DSCALE 0.17677669529663687f   // 1/sqrt(32)
#define NEH ((size_t)NE * HH)

// ---------------- device scratch ----------------
__device__ int   g_n2s[NN];
__device__ unsigned char g_nneed[NN];
__device__ unsigned char g_eneed[NE];
__device__ int   g_deg[UCNT];
__device__ int   g_eidx[UCNT * MAXDEG];
__device__ int   g_nbr[UCNT * MAXDEG];
__device__ int   g_Lcnt, g_Ecnt;
__device__ int   g_Llist[NN], g_nodeL[NN];
__device__ int   g_Elist[NE], g_eE[NE];
__device__ int   g_tgtL[UCNT], g_canon[UCNT], g_hasnbr[UCNT];
__device__ int   g_rowSlot[NN];

__device__ float g_xL[NN * HH];
__device__ float g_tfL[NN * HH];
__device__ float g_Ak[NN * HH];
__device__ float g_Av[NN * HH];
__device__ float g_tfe[2 * NE * HH];
__device__ float g_Bk[2 * NE * HH];
__device__ float g_Bv[2 * NE * HH];
__device__ float g_q[UCNT * HH];
__device__ float g_o[UCNT * HH];
__device__ float g_attn[UCNT * HH];
__device__ float g_agg[UCNT * HH];
__device__ float g_e1[UCNT * HH];
__device__ float g_emb[UCNT * 64];
__device__ float g_z1[128 * HH];
__device__ float g_z2[128 * 64];

#define WT_TOTAL 294912
__device__ float g_Wt[WT_TOTAL];

__constant__ int c_moutD[19] = {128,128,128,128,128,128,128,128,128,
                                128,128,128,128,128,128,128, 64,128, 64};
__constant__ int c_moff[19]  = {0,16384,32768,49152,65536,81920,98304,114688,
                                131072,147456,163840,180224,196608,212992,
                                229376,245760,262144,270336,286720};
static const int h_moff[19]  = {0,16384,32768,49152,65536,81920,98304,114688,
                                131072,147456,163840,180224,196608,212992,
                                229376,245760,262144,270336,286720};

struct WPtrs { const float* p[19]; };

// ---------------- setup ----------------
__global__ void k_init() {
    int i = blockIdx.x * blockDim.x + threadIdx.x;
    if (i < NN) { g_n2s[i] = -1; g_nneed[i] = 0; g_rowSlot[i] = -1; }
    if (i < NE) g_eneed[i] = 0;
    if (i < UCNT) g_deg[i] = 0;
    if (i == 0) { g_Lcnt = 0; g_Ecnt = 0; }
}

__global__ void k_mark(const int* __restrict__ tp) {
    int u = threadIdx.x;
    if (u < UCNT) {
        int t = tp[u];
        atomicMax(&g_n2s[t], u);   // max-u == serial last-write-wins
        g_nneed[t] = 1;
    }
}

__global__ void k_scan(const int* __restrict__ src, const int* __restrict__ dst) {
    int i = blockIdx.x * blockDim.x + threadIdx.x;
    if (i >= NE) return;
    int s = src[i], d = dst[i];
    int su = g_n2s[s];
    if (su >= 0) {
        int j = atomicAdd(&g_deg[su], 1);
        if (j < MAXDEG) { g_eidx[su * MAXDEG + j] = i; g_nbr[su * MAXDEG + j] = d; }
        g_eneed[i] = 1; g_nneed[d] = 1;
    }
    int du = g_n2s[d];
    if (du >= 0 && d != s) {
        int j = atomicAdd(&g_deg[du], 1);
        if (j < MAXDEG) { g_eidx[du * MAXDEG + j] = i; g_nbr[du * MAXDEG + j] = s; }
        g_eneed[i] = 1; g_nneed[s] = 1;
    }
}

__global__ void k_compactNE() {
    int i = blockIdx.x * blockDim.x + threadIdx.x;
    if (i < NN && g_nneed[i]) {
        int p = atomicAdd(&g_Lcnt, 1);
        g_Llist[p] = i; g_nodeL[i] = p;
    }
    if (i < NE && g_eneed[i]) {
        int p = atomicAdd(&g_Ecnt, 1);
        g_Elist[p] = i; g_eE[i] = p;
    }
}

// block per slot: smem insertion sort by edge id + finalize
__global__ void k_sortfin(const int* __restrict__ tp) {
    int u = blockIdx.x, lane = threadIdx.x;
    __shared__ int se[MAXDEG], sn[MAXDEG];
    int dg = g_deg[u]; if (dg > MAXDEG) dg = MAXDEG;
    for (int j = lane; j < dg; j += 32) {
        se[j] = g_eidx[u * MAXDEG + j];
        sn[j] = g_nbr[u * MAXDEG + j];
    }
    __syncwarp();
    if (lane == 0) {
        g_deg[u] = dg;
        for (int i = 1; i < dg; i++) {
            int ke = se[i], kn = sn[i], j = i - 1;
            while (j >= 0 && se[j] > ke) { se[j+1] = se[j]; sn[j+1] = sn[j]; j--; }
            se[j+1] = ke; sn[j+1] = kn;
        }
        int t = tp[u];
        int nl = g_nodeL[t];
        g_tgtL[u] = nl;
        int c = g_n2s[t];
        g_canon[u] = c;
        g_hasnbr[u] = (g_deg[c] > 0 || (c != u && dg > 0)) ? (g_deg[c] > 0 ? 1 : 0) : (dg > 0 ? 1 : 0);
        g_hasnbr[u] = (g_deg[c] > 0) ? 1 : 0;
        if (c == u) g_rowSlot[nl] = u;
    }
    __syncwarp();
    for (int j = lane; j < dg; j += 32) {
        g_eidx[u * MAXDEG + j] = se[j];
        g_nbr[u * MAXDEG + j] = sn[j];
    }
}

__global__ void k_transpose(WPtrs ws) {
    int m = blockIdx.y;
    int outD = c_moutD[m];
    int total = outD * 128;
    int i = blockIdx.x * blockDim.x + threadIdx.x;
    if (i >= total) return;
    int k = i / outD, j = i - k * outD;
    g_Wt[c_moff[m] + i] = ws.p[m][j * 128 + k];
}

// ---------------- batched GEMM, weights in smem ----------------
struct Job {
    const float* in; const float* aux; const float* aux2; const float* bias;
    float* out;
    int gsel, woff, cntsel, outD, relu;
};
struct JobSet { Job j[4]; int n; };

#define DSM ((16384 + 16 * HH) * 4)

__device__ __forceinline__ float4 relu4(float4 v) {
    v.x = fmaxf(v.x, 0.f); v.y = fmaxf(v.y, 0.f);
    v.z = fmaxf(v.z, 0.f); v.w = fmaxf(v.w, 0.f);
    return v;
}

__global__ void __launch_bounds__(128)
k_gemm(JobSet js) {
    extern __shared__ float sm[];
    float* s_w = sm;
    float (*s_in)[HH] = (float(*)[HH])(sm + 16384);
    int tid = threadIdx.x, w = tid >> 5, lane = tid & 31;
    int k4 = lane * 4;

    int cnts[4], pre[5];
    pre[0] = 0;
    for (int j = 0; j < js.n; j++) {
        int cs = js.j[j].cntsel;
        int c = (cs == 0) ? g_Lcnt : (cs == 1) ? g_Ecnt : (cs == 2) ? UCNT : 128;
        cnts[j] = c;
        pre[j + 1] = pre[j] + ((c + 15) >> 4);
    }
    int T = pre[js.n];
    int per = (T + gridDim.x - 1) / gridDim.x;
    int t0 = blockIdx.x * per;
    int t1 = min(T, t0 + per);
    int cur = -1;

    for (int t = t0; t < t1; t++) {
        int j = 0;
        while (t >= pre[j + 1]) j++;
        Job jb = js.j[j];
        int od4 = jb.outD >> 2;
        bool act = k4 < jb.outD;
        if (j != cur) {
            const float4* gw = (const float4*)(g_Wt + jb.woff);
            int tot = HH * od4;
            for (int i = tid; i < tot; i += 128)
                ((float4*)s_w)[i] = gw[i];
            cur = j;
        }
        int cnt = cnts[j];
        int r0 = (t - pre[j]) * 16;

        for (int rr = w; rr < 16; rr += 4) {
            int r = r0 + rr;
            int rc = (r < cnt) ? r : (cnt - 1);
            float4 v;
            switch (jb.gsel) {
            case 0: v = *(const float4*)(jb.in + (size_t)rc * HH + k4); break;
            case 1: v = *(const float4*)(jb.in + (size_t)g_Llist[rc] * HH + k4); break;
            case 2: v = *(const float4*)(jb.in + (size_t)g_tgtL[rc] * HH + k4); break;
            case 3: {
                int s = g_rowSlot[rc];
                const float* src = (s >= 0) ? (jb.aux + (size_t)s * HH)
                                            : (jb.in + (size_t)rc * HH);
                v = relu4(*(const float4*)(src + k4));
            } break;
            case 4:
                v = relu4(*(const float4*)(jb.in + (size_t)g_canon[rc] * HH + k4));
                break;
            case 5: {
                const float* src = (k4 < 64) ? (jb.in + (size_t)(2 * rc) * 64 + k4)
                                             : (jb.in + (size_t)(2 * rc + 1) * 64 + (k4 - 64));
                v = *(const float4*)src;
            } break;
            case 6: {
                const float* src = g_hasnbr[rc] ? (jb.in + (size_t)rc * HH)
                                                : (jb.aux + (size_t)g_tgtL[rc] * HH);
                v = *(const float4*)(src + k4);
            } break;
            default: { // 7: on-the-fly time encoder stage 1
                float tv = jb.in[g_Elist[rc]];
                float4 w1 = *(const float4*)(jb.aux + k4);
                float4 b1 = *(const float4*)(jb.aux2 + k4);
                v.x = fmaxf(fmaf(tv, w1.x, b1.x), 0.f);
                v.y = fmaxf(fmaf(tv, w1.y, b1.y), 0.f);
                v.z = fmaxf(fmaf(tv, w1.z, b1.z), 0.f);
                v.w = fmaxf(fmaf(tv, w1.w, b1.w), 0.f);
            } break;
            }
            *(float4*)(&s_in[rr][k4]) = v;
        }
        __syncthreads();

        float acc[4][4];
#pragma unroll
        for (int r = 0; r < 4; r++)
            acc[r][0] = acc[r][1] = acc[r][2] = acc[r][3] = 0.f;

#pragma unroll 4
        for (int k = 0; k < HH; k++) {
            float4 wv = act ? ((const float4*)s_w)[k * od4 + lane]
                            : make_float4(0.f, 0.f, 0.f, 0.f);
#pragma unroll
            for (int r = 0; r < 4; r++) {
                float xv = s_in[w * 4 + r][k];
                acc[r][0] = fmaf(xv, wv.x, acc[r][0]);
                acc[r][1] = fmaf(xv, wv.y, acc[r][1]);
                acc[r][2] = fmaf(xv, wv.z, acc[r][2]);
                acc[r][3] = fmaf(xv, wv.w, acc[r][3]);
            }
        }
        float4 bv = (jb.bias != nullptr && act) ? ((const float4*)jb.bias)[lane]
                                                : make_float4(0.f, 0.f, 0.f, 0.f);
#pragma unroll
        for (int r = 0; r < 4; r++) {
            int row = r0 + w * 4 + r;
            if (row < cnt && act) {
                float4 o;
                o.x = acc[r][0] + bv.x; o.y = acc[r][1] + bv.y;
                o.z = acc[r][2] + bv.z; o.w = acc[r][3] + bv.w;
                if (jb.relu) o = relu4(o);
                *(float4*)(jb.out + (size_t)row * jb.outD + k4) = o;
            }
        }
        __syncthreads();
    }
}

// ---------------- attention ----------------
__global__ void __launch_bounds__(128)
k_attn(const float* __restrict__ pBk, const float* __restrict__ pBv) {
    int u = blockIdx.x;
    int cu = g_canon[u];
    int dg = g_deg[cu];
    __shared__ int   sRow[MAXDEG];
    __shared__ int   sJe[MAXDEG];
    __shared__ float sSc[MAXDEG][5];
    int tid = threadIdx.x, w = tid >> 5, lane = tid & 31;
    int k4 = lane * 4;

    for (int j = tid; j < dg; j += 128) {
        sRow[j] = g_nodeL[g_nbr[cu * MAXDEG + j]];
        sJe[j]  = g_eE[g_eidx[cu * MAXDEG + j]];
    }
    __syncthreads();

    // phase 1: scores, warp per edge (4-way edge parallel)
    float4 q4 = *(const float4*)(g_q + (size_t)u * HH + k4);
    for (int j = w; j < dg; j += 4) {
        const float* a = g_Ak + (size_t)sRow[j] * HH;
        const float* b = pBk + (size_t)sJe[j] * HH;
        float4 av = *(const float4*)(a + k4);
        float4 bb = *(const float4*)(b + k4);
        float d = q4.x * (av.x + bb.x) + q4.y * (av.y + bb.y)
                + q4.z * (av.z + bb.z) + q4.w * (av.w + bb.w);
        d += __shfl_xor_sync(0xffffffffu, d, 4);
        d += __shfl_xor_sync(0xffffffffu, d, 2);
        d += __shfl_xor_sync(0xffffffffu, d, 1);
        if ((lane & 7) == 0) sSc[j][lane >> 3] = d * DSCALE;
    }
    __syncthreads();

    // phase 2: softmax, warp per head
    {
        float mx = -1e30f;
        for (int j = lane; j < dg; j += 32) mx = fmaxf(mx, sSc[j][w]);
#pragma unroll
        for (int m = 16; m > 0; m >>= 1)
            mx = fmaxf(mx, __shfl_xor_sync(0xffffffffu, mx, m));
        float sm = 0.f;
        for (int j = lane; j < dg; j += 32) {
            float p = expf(sSc[j][w] - mx);
            sSc[j][w] = p;
            sm += p;
        }
#pragma unroll
        for (int m = 16; m > 0; m >>= 1)
            sm += __shfl_xor_sync(0xffffffffu, sm, m);
        float inv = (dg > 0) ? (1.f / sm) : 0.f;
        for (int j = lane; j < dg; j += 32) sSc[j][w] *= inv;
    }
    __syncthreads();

    // phase 3: weighted sum, thread per output dim, deterministic ascending j
    int i = tid, h = tid >> 5;
    float acc = 0.f;
    for (int j = 0; j < dg; j++) {
        acc = fmaf(sSc[j][h],
                   g_Av[(size_t)sRow[j] * HH + i] + pBv[(size_t)sJe[j] * HH + i],
                   acc);
    }
    g_o[(size_t)u * HH + i] = acc;
}

// ---------------- final dot + sigmoid ----------------
__global__ void k_lp3(const float* __restrict__ W, const float* __restrict__ b,
                      float* __restrict__ out) {
    int gid = blockIdx.x * blockDim.x + threadIdx.x;
    int p = gid >> 5, lane = gid & 31;
    if (p >= 128) return;
    float a = g_z2[p * 64 + lane] * W[lane] + g_z2[p * 64 + 32 + lane] * W[32 + lane];
#pragma unroll
    for (int m = 16; m > 0; m >>= 1) a += __shfl_xor_sync(0xffffffffu, a, m);
    if (lane == 0) out[p] = 1.f / (1.f + expf(-(a + b[0])));
}

// ---------------- launch ----------------
static inline Job mkJob(const float* in, const float* aux, const float* aux2,
                        const float* bias, float* out, int gsel, int woff,
                        int cntsel, int outD, int relu) {
    Job j; j.in = in; j.aux = aux; j.aux2 = aux2; j.bias = bias; j.out = out;
    j.gsel = gsel; j.woff = woff; j.cntsel = cntsel; j.outD = outD; j.relu = relu;
    return j;
}

extern "C" void kernel_launch(void* const* d_in, const int* in_sizes, int n_in,
                              void* d_out, int out_size) {
    const float* nf   = (const float*)d_in[0];
    const int*   eidx = (const int*)d_in[1];
    const float* ets  = (const float*)d_in[2];
    const int*   tp   = (const int*)d_in[3];
    const float* in_W = (const float*)d_in[4];
    const float* in_b = (const float*)d_in[5];
    const float* teW1 = (const float*)d_in[6];
    const float* teB1 = (const float*)d_in[7];
    const float* teW2 = (const float*)d_in[8];
    const float* teB2 = (const float*)d_in[9];
    const float* aiW  = (const float*)d_in[10];
    const float* aiB  = (const float*)d_in[11];
    const float* aoW  = (const float*)d_in[12];
    const float* aoB  = (const float*)d_in[13];
    const float* ftW  = (const float*)d_in[14];
    const float* ftB  = (const float*)d_in[15];
    const float* opW  = (const float*)d_in[16];
    const float* opB  = (const float*)d_in[17];
    const float* o1W  = (const float*)d_in[18];
    const float* o1B  = (const float*)d_in[19];
    const float* o2W  = (const float*)d_in[20];
    const float* o2B  = (const float*)d_in[21];
    const float* l1W  = (const float*)d_in[22];
    const float* l1B  = (const float*)d_in[23];
    const float* l2W  = (const float*)d_in[24];
    const float* l2B  = (const float*)d_in[25];
    const float* l3W  = (const float*)d_in[26];
    const float* l3B  = (const float*)d_in[27];
    float* out = (float*)d_out;

    const int* src = eidx;
    const int* dst = eidx + NE;

    // device buffer addresses
    float *p_xL, *p_tfL, *p_Ak, *p_Av, *p_tfe, *p_Bk, *p_Bv, *p_q, *p_o,
          *p_attn, *p_agg, *p_e1, *p_emb, *p_z1;
    cudaGetSymbolAddress((void**)&p_xL,  g_xL);
    cudaGetSymbolAddress((void**)&p_tfL, g_tfL);
    cudaGetSymbolAddress((void**)&p_Ak,  g_Ak);
    cudaGetSymbolAddress((void**)&p_Av,  g_Av);
    cudaGetSymbolAddress((void**)&p_tfe, g_tfe);
    cudaGetSymbolAddress((void**)&p_Bk,  g_Bk);
    cudaGetSymbolAddress((void**)&p_Bv,  g_Bv);
    cudaGetSymbolAddress((void**)&p_q,   g_q);
    cudaGetSymbolAddress((void**)&p_o,   g_o);
    cudaGetSymbolAddress((void**)&p_attn,g_attn);
    cudaGetSymbolAddress((void**)&p_agg, g_agg);
    cudaGetSymbolAddress((void**)&p_e1,  g_e1);
    cudaGetSymbolAddress((void**)&p_emb, g_emb);
    cudaGetSymbolAddress((void**)&p_z1,  g_z1);
    float* p_z2; cudaGetSymbolAddress((void**)&p_z2, g_z2);

    cudaFuncSetAttribute(k_gemm, cudaFuncAttributeMaxDynamicSharedMemorySize, DSM);

    // setup
    k_init<<<(NE + 255) / 256, 256>>>();
    k_mark<<<1, 256>>>(tp);
    k_scan<<<(NE + 255) / 256, 256>>>(src, dst);
    k_compactNE<<<(NE + 255) / 256, 256>>>();
    k_sortfin<<<UCNT, 32>>>(tp);

    WPtrs ws;
    ws.p[0] = in_W;
    for (int l = 0; l < 2; l++) {
        ws.p[1 + 7*l] = ftW + l * 16384;
        ws.p[2 + 7*l] = teW2 + l * 16384;
        ws.p[3 + 7*l] = aiW + l * 384 * 128;            // Wq
        ws.p[4 + 7*l] = aiW + l * 384 * 128 + 16384;    // Wk
        ws.p[5 + 7*l] = aiW + l * 384 * 128 + 32768;    // Wv
        ws.p[6 + 7*l] = aoW + l * 16384;
        ws.p[7 + 7*l] = opW + l * 16384;
    }
    ws.p[15] = o1W; ws.p[16] = o2W; ws.p[17] = l1W; ws.p[18] = l2W;
    {
        dim3 g(64, 19);
        k_transpose<<<g, 256>>>(ws);
    }

    const int G = 148;
    JobSet s;

    // tfe for both layers (time-encoder folded into row load)
    s.n = 2;
    s.j[0] = mkJob(ets, teW1,       teB1,       teB2,       p_tfe,       7, h_moff[2], 1, 128, 0);
    s.j[1] = mkJob(ets, teW1 + 128, teB1 + 128, teB2 + 128, p_tfe + NEH, 7, h_moff[9], 1, 128, 0);
    k_gemm<<<G, 128, DSM>>>(s);

    // Bk/Bv for both layers
    s.n = 4;
    s.j[0] = mkJob(p_tfe,       0, 0, aiB + 128,       p_Bk,       0, h_moff[4],  1, 128, 0);
    s.j[1] = mkJob(p_tfe,       0, 0, aiB + 256,       p_Bv,       0, h_moff[5],  1, 128, 0);
    s.j[2] = mkJob(p_tfe + NEH, 0, 0, aiB + 384 + 128, p_Bk + NEH, 0, h_moff[11], 1, 128, 0);
    s.j[3] = mkJob(p_tfe + NEH, 0, 0, aiB + 384 + 256, p_Bv + NEH, 0, h_moff[12], 1, 128, 0);
    k_gemm<<<G, 128, DSM>>>(s);

    // x = nf[Llist] @ in_W.T + b
    s.n = 1;
    s.j[0] = mkJob(nf, 0, 0, in_b, p_xL, 1, h_moff[0], 0, 128, 0);
    k_gemm<<<G, 128, DSM>>>(s);

    for (int l = 0; l < 2; l++) {
        int mft = 1 + 7*l, mq = 3 + 7*l, mk = 4 + 7*l, mv = 5 + 7*l,
            mao = 6 + 7*l, mop = 7 + 7*l;

        // tf: layer 0 direct; layer 1 folds relu(scatter(agg)) into row load
        s.n = 1;
        if (l == 0)
            s.j[0] = mkJob(p_xL, 0,     0, ftB,       p_tfL, 0, h_moff[mft], 0, 128, 0);
        else
            s.j[0] = mkJob(p_xL, p_agg, 0, ftB + 128, p_tfL, 3, h_moff[mft], 0, 128, 0);
        k_gemm<<<G, 128, DSM>>>(s);

        // Ak, Av (no bias), q (target gather + bias)
        s.n = 3;
        s.j[0] = mkJob(p_tfL, 0, 0, nullptr,      p_Ak, 0, h_moff[mk], 0, 128, 0);
        s.j[1] = mkJob(p_tfL, 0, 0, nullptr,      p_Av, 0, h_moff[mv], 0, 128, 0);
        s.j[2] = mkJob(p_tfL, 0, 0, aiB + l*384,  p_q,  2, h_moff[mq], 2, 128, 0);
        k_gemm<<<G, 128, DSM>>>(s);

        k_attn<<<UCNT, 128>>>(p_Bk + (size_t)l * NEH, p_Bv + (size_t)l * NEH);

        s.n = 1;
        s.j[0] = mkJob(p_o, 0, 0, aoB + l*128, p_attn, 0, h_moff[mao], 2, 128, 0);
        k_gemm<<<G, 128, DSM>>>(s);

        // op with has-neighbor select folded into row load
        s.n = 1;
        s.j[0] = mkJob(p_attn, p_tfL, 0, opB + l*128, p_agg, 6, h_moff[mop], 2, 128, 0);
        k_gemm<<<G, 128, DSM>>>(s);
    }

    // out1: relu(agg[canon]) input, relu output
    s.n = 1;
    s.j[0] = mkJob(p_agg, 0, 0, o1B, p_e1, 4, h_moff[15], 2, 128, 1);
    k_gemm<<<G, 128, DSM>>>(s);
    // out2 -> emb
    s.n = 1;
    s.j[0] = mkJob(p_e1, 0, 0, o2B, p_emb, 0, h_moff[16], 2, 64, 0);
    k_gemm<<<G, 128, DSM>>>(s);
    // lp1 with pair-concat folded into row load
    s.n = 1;
    s.j[0] = mkJob(p_emb, 0, 0, l1B, p_z1, 5, h_moff[17], 3, 128, 1);
    k_gemm<<<G, 128, DSM>>>(s);
    // lp2
    s.n = 1;
    s.j[0] = mkJob(p_z1, 0, 0, l2B, p_z2, 0, h_moff[18], 3, 64, 1);
    k_gemm<<<G, 128, DSM>>>(s);

    k_lp3<<<32, 128>>>(l3W, l3B, out);
}

// round 4
// speedup vs baseline: 2.7335x; 1.1887x over previous
#include <cuda_runtime.h>
#include <math.h>

#define NN 20000
#define NE 50000
#define HH 128
#define UCNT 256
#define MAXDEG 512
#define DSCALE 0.17677669529663687f   // 1/sqrt(32)
#define NEH ((size_t)NE * HH)
#define NTHR 128
#define MAXB 148
#define SMEM_SZ 73728   // 16384 fl weights + 16*128 fl input tile

// ---------------- device scratch (static, no allocation) ----------------
__device__ int   g_n2s[NN];
__device__ unsigned char g_nneed[NN];
__device__ unsigned char g_eneed[NE];
__device__ int   g_deg[UCNT];
__device__ int   g_eidx[UCNT * MAXDEG];
__device__ int   g_nbr[UCNT * MAXDEG];
__device__ int   g_Lcnt, g_Ecnt;
__device__ int   g_Llist[NN], g_nodeL[NN];
__device__ int   g_Elist[NE], g_eE[NE];
__device__ int   g_tgtL[UCNT], g_canon[UCNT], g_hasnbr[UCNT];
__device__ int   g_rowSlot[NN];

__device__ float g_xL[NN * HH];
__device__ float g_tfL[NN * HH];
__device__ float g_Ak[NN * HH];
__device__ float g_Av[NN * HH];
__device__ float g_tfe[2 * NE * HH];
__device__ float g_Bk[2 * NE * HH];
__device__ float g_Bv[2 * NE * HH];
__device__ float g_q[UCNT * HH];
__device__ float g_agg[UCNT * HH];
__device__ float g_e1[UCNT * HH];
__device__ float g_emb[UCNT * 64];
__device__ float g_z1[128 * HH];

#define WT_TOTAL 294912
__device__ float g_Wt[WT_TOTAL];

__constant__ int c_moutD[19] = {128,128,128,128,128,128,128,128,128,
                                128,128,128,128,128,128,128, 64,128, 64};
__constant__ int c_moff[19]  = {0,16384,32768,49152,65536,81920,98304,114688,
                                131072,147456,163840,180224,196608,212992,
                                229376,245760,262144,270336,286720};

// ---------------- device-wide barrier (8-group tree + epoch spin) ------
__device__ unsigned g_cnt8[8];
__device__ unsigned g_rootc;
__device__ volatile unsigned g_ep;

__device__ __forceinline__ void gridsync() {
    __syncthreads();
    if (threadIdx.x == 0) {
        unsigned nb = gridDim.x;
        unsigned e = g_ep;                 // read current epoch first
        __threadfence();                   // make this block's writes visible
        unsigned g = blockIdx.x & 7u;
        unsigned sz = nb / 8u + ((g < (nb & 7u)) ? 1u : 0u);
        if (atomicAdd(&g_cnt8[g], 1u) == sz - 1u) {
            g_cnt8[g] = 0u;
            __threadfence();
            if (atomicAdd(&g_rootc, 1u) == 7u) {
                g_rootc = 0u;
                __threadfence();
                g_ep = e + 1u;             // release
            }
        }
        while (g_ep == e) { }              // spin (volatile L2 read)
        __threadfence();
    }
    __syncthreads();
}

// ---------------- helpers ----------------
__device__ __forceinline__ float4 relu4(float4 v) {
    v.x = fmaxf(v.x, 0.f); v.y = fmaxf(v.y, 0.f);
    v.z = fmaxf(v.z, 0.f); v.w = fmaxf(v.w, 0.f);
    return v;
}

struct DJob {
    const float* in; const float* aux; const float* aux2; const float* bias;
    float* out;
    int gsel, woff, cnt, outD, relu;   // relu: 0 none, 1 relu, 2 relu+sigmoid-dot epilogue
};

// ---------------- generic batched row-GEMM, weights staged in smem -----
__device__ void run_jobs(float* sm, const DJob* js, int n) {
    float* s_w = sm;
    float (*s_in)[HH] = (float(*)[HH])(sm + 16384);
    int tid = threadIdx.x, w = tid >> 5, lane = tid & 31;
    int k4 = lane * 4;

    int pre[6];
    pre[0] = 0;
    for (int j = 0; j < n; j++) pre[j + 1] = pre[j] + ((js[j].cnt + 15) >> 4);
    int T = pre[n];
    int per = (T + gridDim.x - 1) / gridDim.x;
    int t0 = blockIdx.x * per;
    int t1 = min(T, t0 + per);
    int cur = -1;

    for (int t = t0; t < t1; t++) {
        int j = 0;
        while (t >= pre[j + 1]) j++;
        DJob jb = js[j];
        int od4 = jb.outD >> 2;
        bool act = k4 < jb.outD;
        if (j != cur) {
            const float4* gw = (const float4*)(g_Wt + jb.woff);
            int tot = HH * od4;
            for (int i = tid; i < tot; i += NTHR)
                ((float4*)s_w)[i] = gw[i];
            cur = j;
        }
        int cnt = jb.cnt;
        int r0 = (t - pre[j]) * 16;

        for (int rr = w; rr < 16; rr += 4) {
            int r = r0 + rr;
            int rc = (r < cnt) ? r : (cnt - 1);
            float4 v;
            switch (jb.gsel) {
            case 0: v = *(const float4*)(jb.in + (size_t)rc * HH + k4); break;
            case 1: v = *(const float4*)(jb.in + (size_t)g_Llist[rc] * HH + k4); break;
            case 2: v = *(const float4*)(jb.in + (size_t)g_tgtL[rc] * HH + k4); break;
            case 3: {   // relu(rowSlot>=0 ? agg[slot] : x[row])
                int s = g_rowSlot[rc];
                const float* src = (s >= 0) ? (jb.aux + (size_t)s * HH)
                                            : (jb.in + (size_t)rc * HH);
                v = relu4(*(const float4*)(src + k4));
            } break;
            case 4:     // relu(agg[canon])
                v = relu4(*(const float4*)(jb.in + (size_t)g_canon[rc] * HH + k4));
                break;
            case 5: {   // pair concat from emb (64+64)
                const float* src = (k4 < 64) ? (jb.in + (size_t)(2 * rc) * 64 + k4)
                                             : (jb.in + (size_t)(2 * rc + 1) * 64 + (k4 - 64));
                v = *(const float4*)src;
            } break;
            default: {  // 7: on-the-fly time-encoder stage 1
                float tv = jb.in[g_Elist[rc]];
                float4 w1 = *(const float4*)(jb.aux + k4);
                float4 b1 = *(const float4*)(jb.aux2 + k4);
                v.x = fmaxf(fmaf(tv, w1.x, b1.x), 0.f);
                v.y = fmaxf(fmaf(tv, w1.y, b1.y), 0.f);
                v.z = fmaxf(fmaf(tv, w1.z, b1.z), 0.f);
                v.w = fmaxf(fmaf(tv, w1.w, b1.w), 0.f);
            } break;
            }
            *(float4*)(&s_in[rr][k4]) = v;
        }
        __syncthreads();

        float acc[4][4];
#pragma unroll
        for (int r = 0; r < 4; r++)
            acc[r][0] = acc[r][1] = acc[r][2] = acc[r][3] = 0.f;

#pragma unroll 4
        for (int k = 0; k < HH; k++) {
            float4 wv = act ? ((const float4*)s_w)[k * od4 + lane]
                            : make_float4(0.f, 0.f, 0.f, 0.f);
#pragma unroll
            for (int r = 0; r < 4; r++) {
                float xv = s_in[w * 4 + r][k];
                acc[r][0] = fmaf(xv, wv.x, acc[r][0]);
                acc[r][1] = fmaf(xv, wv.y, acc[r][1]);
                acc[r][2] = fmaf(xv, wv.z, acc[r][2]);
                acc[r][3] = fmaf(xv, wv.w, acc[r][3]);
            }
        }
        float4 bv = (jb.bias != nullptr && act) ? ((const float4*)jb.bias)[lane]
                                                : make_float4(0.f, 0.f, 0.f, 0.f);
        if (jb.relu == 2) {
            // fused lp2-relu + z2.l3W dot + sigmoid
            float4 w3 = act ? *(const float4*)(jb.aux + k4)
                            : make_float4(0.f, 0.f, 0.f, 0.f);
            float b3 = jb.aux2[0];
#pragma unroll
            for (int r = 0; r < 4; r++) {
                int row = r0 + w * 4 + r;
                float4 o;
                o.x = fmaxf(acc[r][0] + bv.x, 0.f);
                o.y = fmaxf(acc[r][1] + bv.y, 0.f);
                o.z = fmaxf(acc[r][2] + bv.z, 0.f);
                o.w = fmaxf(acc[r][3] + bv.w, 0.f);
                float part = o.x * w3.x + o.y * w3.y + o.z * w3.z + o.w * w3.w;
                part += __shfl_xor_sync(0xffffffffu, part, 8);
                part += __shfl_xor_sync(0xffffffffu, part, 4);
                part += __shfl_xor_sync(0xffffffffu, part, 2);
                part += __shfl_xor_sync(0xffffffffu, part, 1);
                if (lane == 0 && row < cnt)
                    jb.out[row] = 1.f / (1.f + expf(-(part + b3)));
            }
        } else {
#pragma unroll
            for (int r = 0; r < 4; r++) {
                int row = r0 + w * 4 + r;
                if (row < cnt && act) {
                    float4 o;
                    o.x = acc[r][0] + bv.x; o.y = acc[r][1] + bv.y;
                    o.z = acc[r][2] + bv.z; o.w = acc[r][3] + bv.w;
                    if (jb.relu) o = relu4(o);
                    *(float4*)(jb.out + (size_t)row * jb.outD + k4) = o;
                }
            }
        }
        __syncthreads();
    }
}

// ---------------- fused attention + attn_out + select + op -------------
__device__ void attn_fused(float* sm, const float* pBk, const float* pBv,
                           const float* Wao, const float* aoB,
                           const float* Wop, const float* opB) {
    int* sRow = (int*)sm;                         // 512 ints
    int* sJe  = sRow + MAXDEG;                    // 512 ints
    float (*sSc)[5] = (float(*)[5])(sm + 1024);   // 512*5 floats
    float* sO = sm + 1024 + MAXDEG * 5;           // 128 floats
    int tid = threadIdx.x, w = tid >> 5, lane = tid & 31;
    int k4 = lane * 4;

    for (int u = blockIdx.x; u < UCNT; u += gridDim.x) {
        int cu = g_canon[u];
        int dg = g_deg[cu];
        for (int j = tid; j < dg; j += NTHR) {
            sRow[j] = g_nodeL[g_nbr[cu * MAXDEG + j]];
            sJe[j]  = g_eE[g_eidx[cu * MAXDEG + j]];
        }
        __syncthreads();

        // scores: warp-per-edge, 8-lane segmented reduce per head
        float4 q4 = *(const float4*)(g_q + (size_t)u * HH + k4);
        for (int j = w; j < dg; j += 4) {
            const float* a = g_Ak + (size_t)sRow[j] * HH;
            const float* b = pBk + (size_t)sJe[j] * HH;
            float4 av = *(const float4*)(a + k4);
            float4 bb = *(const float4*)(b + k4);
            float d = q4.x * (av.x + bb.x) + q4.y * (av.y + bb.y)
                    + q4.z * (av.z + bb.z) + q4.w * (av.w + bb.w);
            d += __shfl_xor_sync(0xffffffffu, d, 4);
            d += __shfl_xor_sync(0xffffffffu, d, 2);
            d += __shfl_xor_sync(0xffffffffu, d, 1);
            if ((lane & 7) == 0) sSc[j][lane >> 3] = d * DSCALE;
        }
        __syncthreads();

        // softmax: warp-per-head
        {
            float mx = -1e30f;
            for (int j = lane; j < dg; j += 32) mx = fmaxf(mx, sSc[j][w]);
#pragma unroll
            for (int m = 16; m > 0; m >>= 1)
                mx = fmaxf(mx, __shfl_xor_sync(0xffffffffu, mx, m));
            float smv = 0.f;
            for (int j = lane; j < dg; j += 32) {
                float p = expf(sSc[j][w] - mx);
                sSc[j][w] = p;
                smv += p;
            }
#pragma unroll
            for (int m = 16; m > 0; m >>= 1)
                smv += __shfl_xor_sync(0xffffffffu, smv, m);
            float inv = (dg > 0) ? (1.f / smv) : 0.f;
            for (int j = lane; j < dg; j += 32) sSc[j][w] *= inv;
        }
        __syncthreads();

        // weighted sum: thread per dim, ascending j (deterministic)
        int h = tid >> 5;
        float acc = 0.f;
        for (int j = 0; j < dg; j++) {
            acc = fmaf(sSc[j][h],
                       g_Av[(size_t)sRow[j] * HH + tid] + pBv[(size_t)sJe[j] * HH + tid],
                       acc);
        }
        sO[tid] = acc;
        __syncthreads();

        // attn = Wao @ o + aoB  (4 partial chains)
        float a0 = 0.f, a1 = 0.f, a2 = 0.f, a3 = 0.f;
#pragma unroll 8
        for (int k = 0; k < HH; k += 4) {
            a0 = fmaf(sO[k],     Wao[(k)     * HH + tid], a0);
            a1 = fmaf(sO[k + 1], Wao[(k + 1) * HH + tid], a1);
            a2 = fmaf(sO[k + 2], Wao[(k + 2) * HH + tid], a2);
            a3 = fmaf(sO[k + 3], Wao[(k + 3) * HH + tid], a3);
        }
        float attn = ((a0 + a1) + (a2 + a3)) + aoB[tid];

        // has-neighbor select
        float ain = g_hasnbr[u] ? attn : g_tfL[(size_t)g_tgtL[u] * HH + tid];
        __syncthreads();
        sO[tid] = ain;
        __syncthreads();

        // agg = Wop @ ain + opB
        a0 = a1 = a2 = a3 = 0.f;
#pragma unroll 8
        for (int k = 0; k < HH; k += 4) {
            a0 = fmaf(sO[k],     Wop[(k)     * HH + tid], a0);
            a1 = fmaf(sO[k + 1], Wop[(k + 1) * HH + tid], a1);
            a2 = fmaf(sO[k + 2], Wop[(k + 2) * HH + tid], a2);
            a3 = fmaf(sO[k + 3], Wop[(k + 3) * HH + tid], a3);
        }
        g_agg[(size_t)u * HH + tid] = ((a0 + a1) + (a2 + a3)) + opB[tid];
        __syncthreads();
    }
}

// ---------------- mega kernel ----------------
struct Params {
    const float* wsrc[19];
    const int *tp, *src, *dst;
    const float *ets, *nf;
    const float *in_b, *teW1, *teB1, *teB2, *aiB, *aoB, *ftB, *opB;
    const float *o1B, *o2B, *l1B, *l2B, *l3W, *l3B;
};

__global__ void __launch_bounds__(NTHR)
k_mega(Params P, float* out) {
    extern __shared__ float sm[];
    const int gt = blockIdx.x * NTHR + threadIdx.x;
    const int gs = gridDim.x * NTHR;

    // ---- S0: init + weight transpose ----
    for (int i = gt; i < NN; i += gs) { g_n2s[i] = -1; g_nneed[i] = 0; g_rowSlot[i] = -1; }
    for (int i = gt; i < NE; i += gs) g_eneed[i] = 0;
    if (gt < UCNT) g_deg[gt] = 0;
    if (gt == 0) { g_Lcnt = 0; g_Ecnt = 0; }
    for (int m = 0; m < 19; m++) {
        int outD = c_moutD[m];
        int tot = outD * 128;
        const float* s = P.wsrc[m];
        for (int i = gt; i < tot; i += gs) {
            int k = i / outD, j = i - k * outD;
            g_Wt[c_moff[m] + i] = s[j * 128 + k];
        }
    }
    gridsync();

    // ---- S1: mark targets (atomicMax == last-write-wins canon) ----
    if (gt < UCNT) {
        int t = P.tp[gt];
        atomicMax(&g_n2s[t], gt);
        g_nneed[t] = 1;
    }
    gridsync();

    // ---- S2: scan edges ----
    for (int i = gt; i < NE; i += gs) {
        int s = P.src[i], d = P.dst[i];
        int su = g_n2s[s];
        if (su >= 0) {
            int j = atomicAdd(&g_deg[su], 1);
            if (j < MAXDEG) { g_eidx[su * MAXDEG + j] = i; g_nbr[su * MAXDEG + j] = d; }
            g_eneed[i] = 1; g_nneed[d] = 1;
        }
        int du = g_n2s[d];
        if (du >= 0 && d != s) {
            int j = atomicAdd(&g_deg[du], 1);
            if (j < MAXDEG) { g_eidx[du * MAXDEG + j] = i; g_nbr[du * MAXDEG + j] = s; }
            g_eneed[i] = 1; g_nneed[s] = 1;
        }
    }
    gridsync();

    // ---- S3: compaction ----
    for (int i = gt; i < NN; i += gs)
        if (g_nneed[i]) { int p = atomicAdd(&g_Lcnt, 1); g_Llist[p] = i; g_nodeL[i] = p; }
    for (int i = gt; i < NE; i += gs)
        if (g_eneed[i]) { int p = atomicAdd(&g_Ecnt, 1); g_Elist[p] = i; g_eE[i] = p; }
    gridsync();

    // ---- S4: sort+finalize, then tfe(l0,l1) + x GEMMs ----
    for (int u = blockIdx.x; u < UCNT; u += gridDim.x) {
        int* se = (int*)sm;
        int* sn = se + MAXDEG;
        int dg = g_deg[u]; if (dg > MAXDEG) dg = MAXDEG;
        for (int j = threadIdx.x; j < dg; j += NTHR) {
            se[j] = g_eidx[u * MAXDEG + j];
            sn[j] = g_nbr[u * MAXDEG + j];
        }
        __syncthreads();
        if (threadIdx.x == 0) {
            g_deg[u] = dg;
            for (int i = 1; i < dg; i++) {
                int ke = se[i], kn = sn[i], j = i - 1;
                while (j >= 0 && se[j] > ke) { se[j+1] = se[j]; sn[j+1] = sn[j]; j--; }
                se[j+1] = ke; sn[j+1] = kn;
            }
            int t = P.tp[u];
            int nl = g_nodeL[t];
            g_tgtL[u] = nl;
            int c = g_n2s[t];
            g_canon[u] = c;
            g_hasnbr[u] = (g_deg[c] > 0) ? 1 : 0;   // benign race: clamp preserves >0
            if (c == u) g_rowSlot[nl] = u;
        }
        __syncthreads();
        for (int j = threadIdx.x; j < dg; j += NTHR) {
            g_eidx[u * MAXDEG + j] = se[j];
            g_nbr[u * MAXDEG + j] = sn[j];
        }
        __syncthreads();
    }
    {
        int Ec = g_Ecnt, Lc = g_Lcnt;
        DJob js[3];
        js[0] = { P.ets, P.teW1,       P.teB1,       P.teB2,       g_tfe,              7, c_moff[2], Ec, 128, 0 };
        js[1] = { P.ets, P.teW1 + 128, P.teB1 + 128, P.teB2 + 128, g_tfe + NEH,        7, c_moff[9], Ec, 128, 0 };
        js[2] = { P.nf,  0, 0,         P.in_b,                     g_xL,               1, c_moff[0], Lc, 128, 0 };
        run_jobs(sm, js, 3);
    }
    gridsync();

    // ---- S5: Bk/Bv (both layers) + tf(l0) ----
    {
        int Ec = g_Ecnt, Lc = g_Lcnt;
        DJob js[5];
        js[0] = { g_tfe,       0, 0, P.aiB + 128,       g_Bk,       0, c_moff[4],  Ec, 128, 0 };
        js[1] = { g_tfe,       0, 0, P.aiB + 256,       g_Bv,       0, c_moff[5],  Ec, 128, 0 };
        js[2] = { g_tfe + NEH, 0, 0, P.aiB + 384 + 128, g_Bk + NEH, 0, c_moff[11], Ec, 128, 0 };
        js[3] = { g_tfe + NEH, 0, 0, P.aiB + 384 + 256, g_Bv + NEH, 0, c_moff[12], Ec, 128, 0 };
        js[4] = { g_xL,        0, 0, P.ftB,             g_tfL,      0, c_moff[1],  Lc, 128, 0 };
        run_jobs(sm, js, 5);
    }
    gridsync();

    for (int l = 0; l < 2; l++) {
        // ---- Ak/Av/q ----
        {
            int Lc = g_Lcnt;
            DJob js[3];
            js[0] = { g_tfL, 0, 0, nullptr,         g_Ak, 0, c_moff[4 + 7*l], Lc,   128, 0 };
            js[1] = { g_tfL, 0, 0, nullptr,         g_Av, 0, c_moff[5 + 7*l], Lc,   128, 0 };
            js[2] = { g_tfL, 0, 0, P.aiB + l * 384, g_q,  2, c_moff[3 + 7*l], UCNT, 128, 0 };
            run_jobs(sm, js, 3);
        }
        gridsync();

        // ---- attention + attn_out + select + op (fused) ----
        attn_fused(sm, g_Bk + (size_t)l * NEH, g_Bv + (size_t)l * NEH,
                   g_Wt + c_moff[6 + 7*l], P.aoB + l * 128,
                   g_Wt + c_moff[7 + 7*l], P.opB + l * 128);
        gridsync();

        // ---- tf(l1) with relu(scatter) folded ----
        if (l == 0) {
            int Lc = g_Lcnt;
            DJob js[1];
            js[0] = { g_xL, g_agg, 0, P.ftB + 128, g_tfL, 3, c_moff[8], Lc, 128, 0 };
            run_jobs(sm, js, 1);
            gridsync();
        }
    }

    // ---- out1 (relu(agg[canon]) in, relu out) ----
    {
        DJob js[1];
        js[0] = { g_agg, 0, 0, P.o1B, g_e1, 4, c_moff[15], UCNT, 128, 1 };
        run_jobs(sm, js, 1);
    }
    gridsync();
    // ---- out2 -> emb ----
    {
        DJob js[1];
        js[0] = { g_e1, 0, 0, P.o2B, g_emb, 0, c_moff[16], UCNT, 64, 0 };
        run_jobs(sm, js, 1);
    }
    gridsync();
    // ---- lp1 (pair concat folded, relu) ----
    {
        DJob js[1];
        js[0] = { g_emb, 0, 0, P.l1B, g_z1, 5, c_moff[17], 128, 128, 1 };
        run_jobs(sm, js, 1);
    }
    gridsync();
    // ---- lp2 + fused lp3 sigmoid-dot epilogue ----
    {
        DJob js[1];
        js[0] = { g_z1, P.l3W, P.l3B, P.l2B, out, 0, c_moff[18], 128, 64, 2 };
        run_jobs(sm, js, 1);
    }
}

// ---------------- launch ----------------
extern "C" void kernel_launch(void* const* d_in, const int* in_sizes, int n_in,
                              void* d_out, int out_size) {
    const float* nf   = (const float*)d_in[0];
    const int*   eidx = (const int*)d_in[1];
    const float* ets  = (const float*)d_in[2];
    const int*   tp   = (const int*)d_in[3];
    const float* in_W = (const float*)d_in[4];
    const float* in_b = (const float*)d_in[5];
    const float* teW1 = (const float*)d_in[6];
    const float* teB1 = (const float*)d_in[7];
    const float* teW2 = (const float*)d_in[8];
    const float* teB2 = (const float*)d_in[9];
    const float* aiW  = (const float*)d_in[10];
    const float* aiB  = (const float*)d_in[11];
    const float* aoW  = (const float*)d_in[12];
    const float* aoB  = (const float*)d_in[13];
    const float* ftW  = (const float*)d_in[14];
    const float* ftB  = (const float*)d_in[15];
    const float* opW  = (const float*)d_in[16];
    const float* opB  = (const float*)d_in[17];
    const float* o1W  = (const float*)d_in[18];
    const float* o1B  = (const float*)d_in[19];
    const float* o2W  = (const float*)d_in[20];
    const float* o2B  = (const float*)d_in[21];
    const float* l1W  = (const float*)d_in[22];
    const float* l1B  = (const float*)d_in[23];
    const float* l2W  = (const float*)d_in[24];
    const float* l2B  = (const float*)d_in[25];
    const float* l3W  = (const float*)d_in[26];
    const float* l3B  = (const float*)d_in[27];
    float* out = (float*)d_out;

    Params P;
    P.wsrc[0] = in_W;
    for (int l = 0; l < 2; l++) {
        P.wsrc[1 + 7*l] = ftW + l * 16384;
        P.wsrc[2 + 7*l] = teW2 + l * 16384;
        P.wsrc[3 + 7*l] = aiW + l * 384 * 128;            // Wq
        P.wsrc[4 + 7*l] = aiW + l * 384 * 128 + 16384;    // Wk
        P.wsrc[5 + 7*l] = aiW + l * 384 * 128 + 32768;    // Wv
        P.wsrc[6 + 7*l] = aoW + l * 16384;
        P.wsrc[7 + 7*l] = opW + l * 16384;
    }
    P.wsrc[15] = o1W; P.wsrc[16] = o2W; P.wsrc[17] = l1W; P.wsrc[18] = l2W;
    P.tp = tp; P.src = eidx; P.dst = eidx + NE;
    P.ets = ets; P.nf = nf;
    P.in_b = in_b; P.teW1 = teW1; P.teB1 = teB1; P.teB2 = teB2;
    P.aiB = aiB; P.aoB = aoB; P.ftB = ftB; P.opB = opB;
    P.o1B = o1B; P.o2B = o2B; P.l1B = l1B; P.l2B = l2B;
    P.l3W = l3W; P.l3B = l3B;

    cudaFuncSetAttribute(k_mega, cudaFuncAttributeMaxDynamicSharedMemorySize, SMEM_SZ);

    // grid sized for guaranteed co-residency (persistent kernel + spin barrier)
    int nSM = MAXB;
    cudaDeviceGetAttribute(&nSM, cudaDevAttrMultiProcessorCount, 0);
    int occ = 1;
    cudaOccupancyMaxActiveBlocksPerMultiprocessor(&occ, k_mega, NTHR, SMEM_SZ);
    int nb = nSM * occ;
    if (nb > MAXB) nb = MAXB;
    if (nb < 8) nb = 8;

    k_mega<<<nb, NTHR, SMEM_SZ>>>(P, out);
}

// round 6
// speedup vs baseline: 2.9045x; 1.0626x over previous
#include <cuda_runtime.h>
#include <math.h>

#define NN 20000
#define NE 50000
#define HH 128
#define UCNT 256
#define MAXDEG 512
#define DSCALE 0.17677669529663687f   // 1/sqrt(32)
#define NTHR 256
#define SMEM_SZ 81920                 // 64KB weights + 16KB row tile

// ---------------- device scratch (static, no allocation) ----------------
__device__ int   g_n2s[NN];          // slot+1; 0 = none
__device__ unsigned char g_nneed[NN];
__device__ int   g_deg[UCNT];
__device__ int   g_eidx[UCNT * MAXDEG];
__device__ int   g_nbr[UCNT * MAXDEG];
__device__ int   g_Lcnt;
__device__ int   g_Llist[NN], g_nodeL[NN];
__device__ int   g_tgtL[UCNT], g_canon[UCNT], g_hasnbr[UCNT];
__device__ int   g_rowSlot[NN];      // slot+1; 0 = none
__device__ int   g_tick[8];

__device__ float g_xL[NN * HH];
__device__ float g_tfL[NN * HH];
__device__ float g_agg[UCNT * HH];
__device__ float g_sv[(size_t)UCNT * MAXDEG * HH];   // per (slot, edge) combined vec

#define WT_TOTAL 294912
__device__ float g_Wt[WT_TOTAL];

__constant__ int c_moutD[19] = {128,128,128,128,128,128,128,128,128,
                                128,128,128,128,128,128,128, 64,128, 64};
__constant__ int c_moff[19]  = {0,16384,32768,49152,65536,81920,98304,114688,
                                131072,147456,163840,180224,196608,212992,
                                229376,245760,262144,270336,286720};

// ---------------- device-wide barrier ----------------
__device__ unsigned g_cnt8[8];
__device__ unsigned g_rootc;
__device__ volatile unsigned g_ep;

__device__ __forceinline__ void gridsync() {
    __syncthreads();
    if (threadIdx.x == 0) {
        unsigned nb = gridDim.x;
        unsigned e = g_ep;
        __threadfence();
        unsigned g = blockIdx.x & 7u;
        unsigned sz = nb / 8u + ((g < (nb & 7u)) ? 1u : 0u);
        if (atomicAdd(&g_cnt8[g], 1u) == sz - 1u) {
            g_cnt8[g] = 0u;
            __threadfence();
            if (atomicAdd(&g_rootc, 1u) == 7u) {
                g_rootc = 0u;
                __threadfence();
                g_ep = e + 1u;
            }
        }
        while (g_ep == e) { }
        __threadfence();
    }
    __syncthreads();
}

// ---------------- helpers ----------------
__device__ __forceinline__ float4 relu4(float4 v) {
    v.x = fmaxf(v.x, 0.f); v.y = fmaxf(v.y, 0.f);
    v.z = fmaxf(v.z, 0.f); v.w = fmaxf(v.w, 0.f);
    return v;
}

// matvec: out_d = sum_k v[k] * Wt[k*stride + d]   (v in smem, Wt in global/L1)
__device__ __forceinline__ float matvec(const float* __restrict__ v,
                                        const float* __restrict__ Wt,
                                        int d, int stride, int K) {
    float a0 = 0.f, a1 = 0.f, a2 = 0.f, a3 = 0.f;
#pragma unroll 8
    for (int k = 0; k < K; k += 4) {
        a0 = fmaf(v[k],     Wt[(k)     * stride + d], a0);
        a1 = fmaf(v[k + 1], Wt[(k + 1) * stride + d], a1);
        a2 = fmaf(v[k + 2], Wt[(k + 2) * stride + d], a2);
        a3 = fmaf(v[k + 3], Wt[(k + 3) * stride + d], a3);
    }
    return (a0 + a1) + (a2 + a3);
}

// ---------------- single-job 32-row-tile GEMM stage (ticket-scheduled) ----
// gsel: 0 linear, 1 Llist gather, 3 relu(rowSlot? agg : in)
__device__ void gemm_stage(float* sm, int sid, const float* __restrict__ in,
                           const float* __restrict__ aux,
                           const float* __restrict__ bias, float* __restrict__ out,
                           int gsel, int woff, int cnt) {
    float* s_w = sm;
    float (*s_in)[HH] = (float(*)[HH])(sm + 16384);
    __shared__ int s_tick;
    int tid = threadIdx.x, w = tid >> 5, lane = tid & 31;
    int k4 = lane * 4;
    int T = (cnt + 31) >> 5;
    bool loaded = false;

    for (;;) {
        if (tid == 0) s_tick = atomicAdd(&g_tick[sid], 1);
        __syncthreads();
        int t = s_tick;
        __syncthreads();
        if (t >= T) break;
        if (!loaded) {
            const float4* gw = (const float4*)(g_Wt + woff);
            for (int i = tid; i < 4096; i += NTHR)
                ((float4*)s_w)[i] = gw[i];
            loaded = true;
        }
        int r0 = t * 32;
        for (int rr = w; rr < 32; rr += 8) {
            int r = r0 + rr;
            int rc = (r < cnt) ? r : (cnt - 1);
            float4 v;
            if (gsel == 0) {
                v = *(const float4*)(in + (size_t)rc * HH + k4);
            } else if (gsel == 1) {
                v = *(const float4*)(in + (size_t)g_Llist[rc] * HH + k4);
            } else {
                int s = g_rowSlot[rc];
                const float* src = (s > 0) ? (aux + (size_t)(s - 1) * HH)
                                           : (in + (size_t)rc * HH);
                v = relu4(*(const float4*)(src + k4));
            }
            *(float4*)(&s_in[rr][k4]) = v;
        }
        __syncthreads();

        float acc[4][4];
#pragma unroll
        for (int r = 0; r < 4; r++)
            acc[r][0] = acc[r][1] = acc[r][2] = acc[r][3] = 0.f;
#pragma unroll 4
        for (int k = 0; k < HH; k++) {
            float4 wv = ((const float4*)s_w)[k * 32 + lane];
#pragma unroll
            for (int r = 0; r < 4; r++) {
                float xv = s_in[w * 4 + r][k];
                acc[r][0] = fmaf(xv, wv.x, acc[r][0]);
                acc[r][1] = fmaf(xv, wv.y, acc[r][1]);
                acc[r][2] = fmaf(xv, wv.z, acc[r][2]);
                acc[r][3] = fmaf(xv, wv.w, acc[r][3]);
            }
        }
        float4 bv = bias ? ((const float4*)bias)[lane] : make_float4(0.f,0.f,0.f,0.f);
#pragma unroll
        for (int r = 0; r < 4; r++) {
            int row = r0 + w * 4 + r;
            if (row < cnt) {
                float4 o;
                o.x = acc[r][0] + bv.x; o.y = acc[r][1] + bv.y;
                o.z = acc[r][2] + bv.z; o.w = acc[r][3] + bv.w;
                *(float4*)(out + (size_t)row * HH + k4) = o;
            }
        }
        __syncthreads();
    }
}

// ---------------- fully-fused attention stage ----------------
__device__ void attn_stage(float* sm, int sid, const float* __restrict__ ets,
                           const float* __restrict__ W1, const float* __restrict__ b1,
                           const float* __restrict__ W2t, const float* __restrict__ b2,
                           const float* __restrict__ Wqt, const float* __restrict__ bq,
                           const float* __restrict__ Wkt, const float* __restrict__ bk,
                           const float* __restrict__ Wvt, const float* __restrict__ bv,
                           const float* __restrict__ Waot, const float* __restrict__ aoB,
                           const float* __restrict__ Wopt, const float* __restrict__ opB) {
    int* sEid = (int*)sm;                       // 512
    int* sRowL = sEid + MAXDEG;                 // 512
    float (*sSc)[4] = (float(*)[4])(sm + 1024); // 512*4
    float* base = sm + 1024 + MAXDEG * 4;
    float* sQ   = base;            // 128
    float* sTgt = base + 128;      // 128
    float (*sH)[HH]   = (float(*)[HH])(base + 256);   // 2*128
    float (*sSum)[HH] = (float(*)[HH])(base + 512);   // 2*128
    float (*sAcc)[HH] = (float(*)[HH])(base + 768);   // 2*128
    float* sO   = base + 1024;     // 128
    __shared__ int s_slot;

    int tid = threadIdx.x;
    int grp = tid >> 7;            // 0/1: edge group
    int d   = tid & 127;           // output dim
    int h   = d >> 5;              // head

    for (;;) {
        if (tid == 0) s_slot = atomicAdd(&g_tick[sid], 1);
        __syncthreads();
        int u = s_slot;
        __syncthreads();
        if (u >= UCNT) break;

        int cu = g_canon[u] - 1;                 // canonical slot (n2s+1 enc)
        int dg = g_deg[cu];
        for (int j = tid; j < dg; j += NTHR) {
            sEid[j] = g_eidx[cu * MAXDEG + j];
            sRowL[j] = g_nodeL[g_nbr[cu * MAXDEG + j]];
        }
        if (tid < 128) sTgt[d] = g_tfL[(size_t)g_tgtL[u] * HH + d];
        __syncthreads();
        if (tid < 128) sQ[d] = matvec(sTgt, Wqt, d, HH, HH) + bq[d];
        __syncthreads();

        int nIt = (dg + 1) >> 1;

        // pass 1: per-edge combined vec + K + score
        for (int it = 0; it < nIt; it++) {
            int j = 2 * it + grp;
            bool live = (j < dg);
            float tv = 0.f; int row = 0;
            if (live) { tv = ets[sEid[j]]; row = sRowL[j]; }
            if (live) sH[grp][d] = fmaxf(fmaf(tv, W1[d], b1[d]), 0.f);
            __syncthreads();
            if (live) {
                float nb = g_tfL[(size_t)row * HH + d];
                float s = nb + matvec(sH[grp], W2t, d, HH, HH) + b2[d];
                sSum[grp][d] = s;
                g_sv[((size_t)u * MAXDEG + j) * HH + d] = s;
            }
            __syncthreads();
            if (live) {
                float kd = matvec(sSum[grp], Wkt, d, HH, HH) + bk[d];
                float sc = sQ[d] * kd;
                sc += __shfl_xor_sync(0xffffffffu, sc, 16);
                sc += __shfl_xor_sync(0xffffffffu, sc, 8);
                sc += __shfl_xor_sync(0xffffffffu, sc, 4);
                sc += __shfl_xor_sync(0xffffffffu, sc, 2);
                sc += __shfl_xor_sync(0xffffffffu, sc, 1);
                if ((d & 31) == 0) sSc[j][h] = sc * DSCALE;
            }
            __syncthreads();
        }

        // pass 2: softmax per head (warps 0-3)
        if (tid < 128) {
            int lane = tid & 31, hh = tid >> 5;
            float mx = -1e30f;
            for (int j = lane; j < dg; j += 32) mx = fmaxf(mx, sSc[j][hh]);
#pragma unroll
            for (int m = 16; m > 0; m >>= 1)
                mx = fmaxf(mx, __shfl_xor_sync(0xffffffffu, mx, m));
            float smv = 0.f;
            for (int j = lane; j < dg; j += 32) {
                float p = expf(sSc[j][hh] - mx);
                sSc[j][hh] = p;
                smv += p;
            }
#pragma unroll
            for (int m = 16; m > 0; m >>= 1)
                smv += __shfl_xor_sync(0xffffffffu, smv, m);
            float inv = (dg > 0) ? (1.f / smv) : 0.f;
            for (int j = lane; j < dg; j += 32) sSc[j][hh] *= inv;
        }
        __syncthreads();

        // pass 3: weighted V sum (recompute V from stored combined vec)
        float accV = 0.f;
        for (int it = 0; it < nIt; it++) {
            int j = 2 * it + grp;
            bool live = (j < dg);
            if (live) sSum[grp][d] = g_sv[((size_t)u * MAXDEG + j) * HH + d];
            __syncthreads();
            if (live) {
                float vd = matvec(sSum[grp], Wvt, d, HH, HH) + bv[d];
                accV = fmaf(sSc[j][h], vd, accV);
            }
            __syncthreads();
        }
        sAcc[grp][d] = accV;
        __syncthreads();
        if (tid < 128) sO[d] = sAcc[0][d] + sAcc[1][d];
        __syncthreads();

        // pass 4: attn_out, select, op
        if (tid < 128) {
            float attn = matvec(sO, Waot, d, HH, HH) + aoB[d];
            float ain = g_hasnbr[u] ? attn : sTgt[d];
            sAcc[0][d] = ain;
        }
        __syncthreads();
        if (tid < 128)
            g_agg[(size_t)u * HH + d] = matvec(sAcc[0], Wopt, d, HH, HH) + opB[d];
        __syncthreads();
    }
}

// ---------------- mega kernel ----------------
struct Params {
    const float* wsrc[19];
    const int *tp, *src, *dst;
    const float *ets, *nf;
    const float *in_b, *teW1, *teB1, *teB2, *aiB, *aoB, *ftB, *opB;
    const float *o1B, *o2B, *l1B, *l2B, *l3W, *l3B;
};

__global__ void __launch_bounds__(NTHR)
k_mega(Params P, float* out) {
    extern __shared__ float sm[];
    const int gt = blockIdx.x * NTHR + threadIdx.x;
    const int gs = gridDim.x * NTHR;
    int tid = threadIdx.x;

    // ---- S0: weight transpose + mark targets ----
    for (int m = 0; m < 19; m++) {
        int outD = c_moutD[m];
        int tot = outD * 128;
        const float* s = P.wsrc[m];
        float* dst = g_Wt + c_moff[m];
        for (int i = gt; i < tot; i += gs) {
            int j = i >> 7, k = i & 127;
            dst[k * outD + j] = s[i];
        }
    }
    if (gt < UCNT) {
        int t = P.tp[gt];
        atomicMax(&g_n2s[t], gt + 1);
        g_nneed[t] = 1;
    }
    gridsync();

    // ---- S1: edge scan ----
    for (int i = gt; i < NE; i += gs) {
        int s = P.src[i], d = P.dst[i];
        int su = g_n2s[s] - 1;
        if (su >= 0) {
            int j = atomicAdd(&g_deg[su], 1);
            if (j < MAXDEG) { g_eidx[su * MAXDEG + j] = i; g_nbr[su * MAXDEG + j] = d; }
            g_nneed[d] = 1;
        }
        int du = g_n2s[d] - 1;
        if (du >= 0 && d != s) {
            int j = atomicAdd(&g_deg[du], 1);
            if (j < MAXDEG) { g_eidx[du * MAXDEG + j] = i; g_nbr[du * MAXDEG + j] = s; }
            g_nneed[s] = 1;
        }
    }
    gridsync();

    // ---- S2: node compaction ----
    for (int i = gt; i < NN; i += gs)
        if (g_nneed[i]) { int p = atomicAdd(&g_Lcnt, 1); g_Llist[p] = i; g_nodeL[i] = p; }
    gridsync();

    // ---- S3: per-slot sort + finalize, then x-GEMM ----
    for (int u = blockIdx.x; u < UCNT; u += gridDim.x) {
        int* se = (int*)sm;
        int* sn = se + MAXDEG;
        int dg = g_deg[u]; if (dg > MAXDEG) dg = MAXDEG;
        for (int j = tid; j < dg; j += NTHR) {
            se[j] = g_eidx[u * MAXDEG + j];
            sn[j] = g_nbr[u * MAXDEG + j];
        }
        __syncthreads();
        if (tid == 0) {
            g_deg[u] = dg;
            for (int i = 1; i < dg; i++) {
                int ke = se[i], kn = sn[i], j = i - 1;
                while (j >= 0 && se[j] > ke) { se[j+1] = se[j]; sn[j+1] = sn[j]; j--; }
                se[j+1] = ke; sn[j+1] = kn;
            }
            int t = P.tp[u];
            int nl = g_nodeL[t];
            g_tgtL[u] = nl;
            int c = g_n2s[t];            // slot+1
            g_canon[u] = c;
            g_hasnbr[u] = (g_deg[c - 1] > 0) ? 1 : 0;
            if (c - 1 == u) g_rowSlot[nl] = u + 1;
        }
        __syncthreads();
        for (int j = tid; j < dg; j += NTHR) {
            g_eidx[u * MAXDEG + j] = se[j];
            g_nbr[u * MAXDEG + j] = sn[j];
        }
        __syncthreads();
    }
    gemm_stage(sm, 0, P.nf, nullptr, P.in_b, g_xL, 1, c_moff[0], g_Lcnt);
    gridsync();

    // ---- S4: tf(l0) ----
    gemm_stage(sm, 1, g_xL, nullptr, P.ftB, g_tfL, 0, c_moff[1], g_Lcnt);
    gridsync();

    // ---- S5: attention layer 0 ----
    attn_stage(sm, 2, P.ets,
               P.teW1, P.teB1, g_Wt + c_moff[2], P.teB2,
               g_Wt + c_moff[3], P.aiB,
               g_Wt + c_moff[4], P.aiB + 128,
               g_Wt + c_moff[5], P.aiB + 256,
               g_Wt + c_moff[6], P.aoB,
               g_Wt + c_moff[7], P.opB);
    gridsync();

    // ---- S6: tf(l1) with relu(scatter) folded ----
    gemm_stage(sm, 3, g_xL, g_agg, P.ftB + 128, g_tfL, 3, c_moff[8], g_Lcnt);
    gridsync();

    // ---- S7: attention layer 1 ----
    attn_stage(sm, 4, P.ets,
               P.teW1 + 128, P.teB1 + 128, g_Wt + c_moff[9], P.teB2 + 128,
               g_Wt + c_moff[10], P.aiB + 384,
               g_Wt + c_moff[11], P.aiB + 384 + 128,
               g_Wt + c_moff[12], P.aiB + 384 + 256,
               g_Wt + c_moff[13], P.aoB + 128,
               g_Wt + c_moff[14], P.opB + 128);
    gridsync();

    // ---- S8: fused tail per pair + cleanup ----
    {
        float (*sAgg)[HH] = (float(*)[HH])sm;            // 2*128
        float (*sE1)[HH]  = (float(*)[HH])(sm + 256);    // 2*128
        float (*sEmb)[64] = (float(*)[64])(sm + 512);    // 2*64
        float* sZ1 = sm + 640;                           // 128
        float* sZ2 = sm + 768;                           // 64
        float* sRed = sm + 832;                          // 2
        int nn = tid >> 7, dd = tid & 127;
        const float* o1Wt = g_Wt + c_moff[15];
        const float* o2Wt = g_Wt + c_moff[16];
        const float* l1Wt = g_Wt + c_moff[17];
        const float* l2Wt = g_Wt + c_moff[18];

        for (int p = blockIdx.x; p < 128; p += gridDim.x) {
            sAgg[nn][dd] = fmaxf(g_agg[(size_t)(2 * p + nn) * HH + dd], 0.f);
            __syncthreads();
            sE1[nn][dd] = fmaxf(matvec(sAgg[nn], o1Wt, dd, HH, HH) + P.o1B[dd], 0.f);
            __syncthreads();
            if (dd < 64)
                sEmb[nn][dd] = matvec(sE1[nn], o2Wt, dd, 64, HH) + P.o2B[dd];
            __syncthreads();
            if (tid < 128) {
                float a0 = 0.f, a1 = 0.f;
#pragma unroll 8
                for (int k = 0; k < 64; k += 2) {
                    a0 = fmaf(sEmb[0][k],     l1Wt[(k)      * HH + dd], a0);
                    a1 = fmaf(sEmb[0][k + 1], l1Wt[(k + 1)  * HH + dd], a1);
                }
#pragma unroll 8
                for (int k = 0; k < 64; k += 2) {
                    a0 = fmaf(sEmb[1][k],     l1Wt[(64 + k)     * HH + dd], a0);
                    a1 = fmaf(sEmb[1][k + 1], l1Wt[(64 + k + 1) * HH + dd], a1);
                }
                sZ1[dd] = fmaxf(a0 + a1 + P.l1B[dd], 0.f);
            }
            __syncthreads();
            if (tid < 64)
                sZ2[tid] = fmaxf(matvec(sZ1, l2Wt, tid, 64, HH) + P.l2B[tid], 0.f);
            __syncthreads();
            if (tid < 64) {
                float part = sZ2[tid] * P.l3W[tid];
                part += __shfl_xor_sync(0xffffffffu, part, 16);
                part += __shfl_xor_sync(0xffffffffu, part, 8);
                part += __shfl_xor_sync(0xffffffffu, part, 4);
                part += __shfl_xor_sync(0xffffffffu, part, 2);
                part += __shfl_xor_sync(0xffffffffu, part, 1);
                if ((tid & 31) == 0) sRed[tid >> 5] = part;
            }
            __syncthreads();
            if (tid == 0)
                out[p] = 1.f / (1.f + expf(-(sRed[0] + sRed[1] + P.l3B[0])));
            __syncthreads();
        }
    }
    // cleanup for next graph replay (restores zero-init invariants)
    for (int i = gt; i < NN; i += gs) g_nneed[i] = 0;
    if (gt < UCNT) {
        g_n2s[P.tp[gt]] = 0;
        g_deg[gt] = 0;
        g_rowSlot[g_tgtL[gt]] = 0;
    }
    if (gt < 8) g_tick[gt] = 0;
    if (gt == 0) g_Lcnt = 0;
}

// ---------------- launch ----------------
extern "C" void kernel_launch(void* const* d_in, const int* in_sizes, int n_in,
                              void* d_out, int out_size) {
    const float* nf   = (const float*)d_in[0];
    const int*   eidx = (const int*)d_in[1];
    const float* ets  = (const float*)d_in[2];
    const int*   tp   = (const int*)d_in[3];
    const float* in_W = (const float*)d_in[4];
    const float* in_b = (const float*)d_in[5];
    const float* teW1 = (const float*)d_in[6];
    const float* teB1 = (const float*)d_in[7];
    const float* teW2 = (const float*)d_in[8];
    const float* teB2 = (const float*)d_in[9];
    const float* aiW  = (const float*)d_in[10];
    const float* aiB  = (const float*)d_in[11];
    const float* aoW  = (const float*)d_in[12];
    const float* aoB  = (const float*)d_in[13];
    const float* ftW  = (const float*)d_in[14];
    const float* ftB  = (const float*)d_in[15];
    const float* opW  = (const float*)d_in[16];
    const float* opB  = (const float*)d_in[17];
    const float* o1W  = (const float*)d_in[18];
    const float* o1B  = (const float*)d_in[19];
    const float* o2W  = (const float*)d_in[20];
    const float* o2B  = (const float*)d_in[21];
    const float* l1W  = (const float*)d_in[22];
    const float* l1B  = (const float*)d_in[23];
    const float* l2W  = (const float*)d_in[24];
    const float* l2B  = (const float*)d_in[25];
    const float* l3W  = (const float*)d_in[26];
    const float* l3B  = (const float*)d_in[27];
    float* out = (float*)d_out;

    Params P;
    P.wsrc[0] = in_W;
    for (int l = 0; l < 2; l++) {
        P.wsrc[1 + 7*l] = ftW + l * 16384;
        P.wsrc[2 + 7*l] = teW2 + l * 16384;
        P.wsrc[3 + 7*l] = aiW + l * 384 * 128;            // Wq
        P.wsrc[4 + 7*l] = aiW + l * 384 * 128 + 16384;    // Wk
        P.wsrc[5 + 7*l] = aiW + l * 384 * 128 + 32768;    // Wv
        P.wsrc[6 + 7*l] = aoW + l * 16384;
        P.wsrc[7 + 7*l] = opW + l * 16384;
    }
    P.wsrc[15] = o1W; P.wsrc[16] = o2W; P.wsrc[17] = l1W; P.wsrc[18] = l2W;
    P.tp = tp; P.src = eidx; P.dst = eidx + NE;
    P.ets = ets; P.nf = nf;
    P.in_b = in_b; P.teW1 = teW1; P.teB1 = teB1; P.teB2 = teB2;
    P.aiB = aiB; P.aoB = aoB; P.ftB = ftB; P.opB = opB;
    P.o1B = o1B; P.o2B = o2B; P.l1B = l1B; P.l2B = l2B;
    P.l3W = l3W; P.l3B = l3B;

    cudaFuncSetAttribute(k_mega, cudaFuncAttributeMaxDynamicSharedMemorySize, SMEM_SZ);

    int nSM = 148;
    cudaDeviceGetAttribute(&nSM, cudaDevAttrMultiProcessorCount, 0);
    int occ = 1;
    cudaOccupancyMaxActiveBlocksPerMultiprocessor(&occ, k_mega, NTHR, SMEM_SZ);
    int nb = nSM * occ;
    if (nb > 296) nb = 296;
    if (nb < 8) nb = 8;

    k_mega<<<nb, NTHR, SMEM_SZ>>>(P, out);
}

// round 7
// speedup vs baseline: 3.2044x; 1.1032x over previous
#include <cuda_runtime.h>
#include <math.h>

#define NN 20000
#define NE 50000
#define HH 128
#define UCNT 256
#define MAXDEG 512
#define DSCALE 0.17677669529663687f   // 1/sqrt(32)
#define NTHR 256
#define SMEM_SZ 81920                 // 64KB weights + 16KB row tile

// ---------------- device scratch (static, no allocation) ----------------
__device__ int   g_n2s[NN];          // slot+1; 0 = none
__device__ unsigned char g_nneed[NN];
__device__ int   g_deg[UCNT];
__device__ int   g_eidx[UCNT * MAXDEG];
__device__ int   g_nbr[UCNT * MAXDEG];
__device__ int   g_Lcnt;
__device__ int   g_Llist[NN], g_nodeL[NN];
__device__ int   g_tgtL[UCNT], g_canon[UCNT], g_hasnbr[UCNT];
__device__ int   g_rowSlot[NN];      // slot+1; 0 = none
__device__ int   g_tick[16];

__device__ int   g_poff[UCNT + 1];
__device__ int   g_Ptot;
__device__ int   g_pSlot[UCNT * MAXDEG];
__device__ float g_pT[UCNT * MAXDEG];
__device__ int   g_pNbrRow[UCNT * MAXDEG];

__device__ float g_xL[NN * HH];
__device__ float g_tfL[NN * HH];
__device__ float g_q[UCNT * HH];
__device__ float g_agg[UCNT * HH];
__device__ float g_s[(size_t)UCNT * MAXDEG * HH];
__device__ float g_V[(size_t)UCNT * MAXDEG * HH];
__device__ float g_sc[UCNT * MAXDEG * 4];

#define WT_TOTAL 294912
__device__ float g_Wt[WT_TOTAL];

__constant__ int c_moutD[19] = {128,128,128,128,128,128,128,128,128,
                                128,128,128,128,128,128,128, 64,128, 64};
__constant__ int c_moff[19]  = {0,16384,32768,49152,65536,81920,98304,114688,
                                131072,147456,163840,180224,196608,212992,
                                229376,245760,262144,270336,286720};

// ---------------- device-wide barrier ----------------
__device__ unsigned g_cnt8[8];
__device__ unsigned g_rootc;
__device__ volatile unsigned g_ep;

__device__ __forceinline__ void gridsync() {
    __syncthreads();
    if (threadIdx.x == 0) {
        unsigned nb = gridDim.x;
        unsigned e = g_ep;
        __threadfence();
        unsigned g = blockIdx.x & 7u;
        unsigned sz = nb / 8u + ((g < (nb & 7u)) ? 1u : 0u);
        if (atomicAdd(&g_cnt8[g], 1u) == sz - 1u) {
            g_cnt8[g] = 0u;
            __threadfence();
            if (atomicAdd(&g_rootc, 1u) == 7u) {
                g_rootc = 0u;
                __threadfence();
                g_ep = e + 1u;
            }
        }
        while (g_ep == e) { }
        __threadfence();
    }
    __syncthreads();
}

// ---------------- helpers ----------------
__device__ __forceinline__ float4 relu4(float4 v) {
    v.x = fmaxf(v.x, 0.f); v.y = fmaxf(v.y, 0.f);
    v.z = fmaxf(v.z, 0.f); v.w = fmaxf(v.w, 0.f);
    return v;
}

__device__ __forceinline__ float matvec(const float* __restrict__ v,
                                        const float* __restrict__ Wt,
                                        int d, int stride, int K) {
    float a0 = 0.f, a1 = 0.f, a2 = 0.f, a3 = 0.f;
#pragma unroll 8
    for (int k = 0; k < K; k += 4) {
        a0 = fmaf(v[k],     Wt[(k)     * stride + d], a0);
        a1 = fmaf(v[k + 1], Wt[(k + 1) * stride + d], a1);
        a2 = fmaf(v[k + 2], Wt[(k + 2) * stride + d], a2);
        a3 = fmaf(v[k + 3], Wt[(k + 3) * stride + d], a3);
    }
    return (a0 + a1) + (a2 + a3);
}

// ---------------- generic tile GEMM stage (ticket-scheduled) ----------------
// gsel: 0 linear, 1 Llist, 2 tgtL, 3 relu(rowSlot? aggAux : in), 4 time-encode
// mode: 0 plain(+bias), 1 +bias+tf[nbrRow] (combined s), 2 q-dot score epilogue
struct GJob {
    const float* in; const float* pA; const float* pB; const float* bias;
    float* out;
    int gsel, mode, woff, cnt, sid;
};

__device__ void gemm_stage(float* sm, GJob jb) {
    float* s_w = sm;
    float (*s_in)[HH] = (float(*)[HH])(sm + 16384);
    __shared__ int s_tick;
    int tid = threadIdx.x, w = tid >> 5, lane = tid & 31;
    int k4 = lane * 4;
    int cnt = jb.cnt;
    int T = (cnt + 31) >> 5;
    bool loaded = false;

    for (;;) {
        if (tid == 0) s_tick = atomicAdd(&g_tick[jb.sid], 1);
        __syncthreads();
        int t = s_tick;
        __syncthreads();
        if (t >= T) break;
        if (!loaded) {
            const float4* gw = (const float4*)(g_Wt + jb.woff);
            for (int i = tid; i < 4096; i += NTHR)
                ((float4*)s_w)[i] = gw[i];
            loaded = true;
        }
        int r0 = t * 32;
        for (int rr = w; rr < 32; rr += 8) {
            int r = r0 + rr;
            int rc = (r < cnt) ? r : (cnt - 1);
            float4 v;
            if (jb.gsel == 0) {
                v = *(const float4*)(jb.in + (size_t)rc * HH + k4);
            } else if (jb.gsel == 1) {
                v = *(const float4*)(jb.in + (size_t)g_Llist[rc] * HH + k4);
            } else if (jb.gsel == 2) {
                v = *(const float4*)(jb.in + (size_t)g_tgtL[rc] * HH + k4);
            } else if (jb.gsel == 3) {
                int s = g_rowSlot[rc];
                const float* src = (s > 0) ? (jb.pA + (size_t)(s - 1) * HH)
                                           : (jb.in + (size_t)rc * HH);
                v = relu4(*(const float4*)(src + k4));
            } else {  // 4: time-encode stage 1
                float tv = g_pT[rc];
                float4 w1 = *(const float4*)(jb.pA + k4);
                float4 b1 = *(const float4*)(jb.pB + k4);
                v.x = fmaxf(fmaf(tv, w1.x, b1.x), 0.f);
                v.y = fmaxf(fmaf(tv, w1.y, b1.y), 0.f);
                v.z = fmaxf(fmaf(tv, w1.z, b1.z), 0.f);
                v.w = fmaxf(fmaf(tv, w1.w, b1.w), 0.f);
            }
            *(float4*)(&s_in[rr][k4]) = v;
        }
        __syncthreads();

        float acc[4][4];
#pragma unroll
        for (int r = 0; r < 4; r++)
            acc[r][0] = acc[r][1] = acc[r][2] = acc[r][3] = 0.f;
#pragma unroll 4
        for (int k = 0; k < HH; k++) {
            float4 wv = ((const float4*)s_w)[k * 32 + lane];
#pragma unroll
            for (int r = 0; r < 4; r++) {
                float xv = s_in[w * 4 + r][k];
                acc[r][0] = fmaf(xv, wv.x, acc[r][0]);
                acc[r][1] = fmaf(xv, wv.y, acc[r][1]);
                acc[r][2] = fmaf(xv, wv.z, acc[r][2]);
                acc[r][3] = fmaf(xv, wv.w, acc[r][3]);
            }
        }
        float4 bv = jb.bias ? ((const float4*)jb.bias)[lane]
                            : make_float4(0.f, 0.f, 0.f, 0.f);
        if (jb.mode == 2) {
            // score epilogue: sc[row][h] = (q[u] . (acc+bk)) * DSCALE
#pragma unroll
            for (int r = 0; r < 4; r++) {
                int row = r0 + w * 4 + r;
                int rowc = (row < cnt) ? row : (cnt - 1);
                int u = g_pSlot[rowc];
                float4 q4 = *(const float4*)(g_q + (size_t)u * HH + k4);
                float p = (acc[r][0] + bv.x) * q4.x + (acc[r][1] + bv.y) * q4.y
                        + (acc[r][2] + bv.z) * q4.z + (acc[r][3] + bv.w) * q4.w;
                p += __shfl_xor_sync(0xffffffffu, p, 4);
                p += __shfl_xor_sync(0xffffffffu, p, 2);
                p += __shfl_xor_sync(0xffffffffu, p, 1);
                if ((lane & 7) == 0 && row < cnt)
                    jb.out[rowc * 4 + (lane >> 3)] = p * DSCALE;
            }
        } else {
#pragma unroll
            for (int r = 0; r < 4; r++) {
                int row = r0 + w * 4 + r;
                if (row < cnt) {
                    float4 o;
                    o.x = acc[r][0] + bv.x; o.y = acc[r][1] + bv.y;
                    o.z = acc[r][2] + bv.z; o.w = acc[r][3] + bv.w;
                    if (jb.mode == 1) {
                        int nr = g_pNbrRow[row];
                        float4 tv = *(const float4*)(g_tfL + (size_t)nr * HH + k4);
                        o.x += tv.x; o.y += tv.y; o.z += tv.z; o.w += tv.w;
                    }
                    *(float4*)(jb.out + (size_t)row * HH + k4) = o;
                }
            }
        }
        __syncthreads();
    }
}

// ---------------- per-slot finish: softmax + weighted V + attn_out + op ----
__device__ void fin_stage(float* sm, int sid,
                          const float* __restrict__ Waot, const float* __restrict__ aoB,
                          const float* __restrict__ Wopt, const float* __restrict__ opB) {
    float* sSc  = sm;                  // MAXDEG*4
    float* sO   = sm + MAXDEG * 4;     // 128
    float* sTgt = sO + 128;            // 128
    float* sTmp = sTgt + 128;          // 128
    __shared__ int s_slot;
    int tid = threadIdx.x;
    int d = tid & 127;
    int h = d >> 5;

    for (;;) {
        if (tid == 0) s_slot = atomicAdd(&g_tick[sid], 1);
        __syncthreads();
        int u = s_slot;
        __syncthreads();
        if (u >= UCNT) break;

        int off = g_poff[u];
        int dg = g_poff[u + 1] - off;
        for (int i = tid; i < dg * 4; i += NTHR) sSc[i] = g_sc[off * 4 + i];
        if (tid < 128) sTgt[d] = g_tfL[(size_t)g_tgtL[u] * HH + d];
        __syncthreads();

        // softmax per head (warps 0-3)
        if (tid < 128) {
            int lane = tid & 31, hh = tid >> 5;
            float mx = -1e30f;
            for (int j = lane; j < dg; j += 32) mx = fmaxf(mx, sSc[j * 4 + hh]);
#pragma unroll
            for (int m = 16; m > 0; m >>= 1)
                mx = fmaxf(mx, __shfl_xor_sync(0xffffffffu, mx, m));
            float smv = 0.f;
            for (int j = lane; j < dg; j += 32) {
                float p = expf(sSc[j * 4 + hh] - mx);
                sSc[j * 4 + hh] = p;
                smv += p;
            }
#pragma unroll
            for (int m = 16; m > 0; m >>= 1)
                smv += __shfl_xor_sync(0xffffffffu, smv, m);
            float inv = (dg > 0) ? (1.f / smv) : 0.f;
            for (int j = lane; j < dg; j += 32) sSc[j * 4 + hh] *= inv;
        }
        __syncthreads();

        // weighted V sum, ascending j (deterministic)
        if (tid < 128) {
            float o = 0.f;
            for (int j = 0; j < dg; j++)
                o = fmaf(sSc[j * 4 + h], g_V[((size_t)(off + j)) * HH + d], o);
            sO[d] = o;
        }
        __syncthreads();

        if (tid < 128) {
            float attn = matvec(sO, Waot, d, HH, HH) + aoB[d];
            sTmp[d] = (dg > 0) ? attn : sTgt[d];
        }
        __syncthreads();
        if (tid < 128)
            g_agg[(size_t)u * HH + d] = matvec(sTmp, Wopt, d, HH, HH) + opB[d];
        __syncthreads();
    }
}

// ---------------- mega kernel ----------------
struct Params {
    const float* wsrc[19];
    const int *tp, *src, *dst;
    const float *ets, *nf;
    const float *in_b, *teW1, *teB1, *teB2, *aiB, *aoB, *ftB, *opB;
    const float *o1B, *o2B, *l1B, *l2B, *l3W, *l3B;
};

__global__ void __launch_bounds__(NTHR)
k_mega(Params P, float* out) {
    extern __shared__ float sm[];
    const int gt = blockIdx.x * NTHR + threadIdx.x;
    const int gs = gridDim.x * NTHR;
    int tid = threadIdx.x;

    // ---- S0: weight transpose + mark targets ----
    for (int m = 0; m < 19; m++) {
        int outD = c_moutD[m];
        int tot = outD * 128;
        const float* s = P.wsrc[m];
        float* dst = g_Wt + c_moff[m];
        for (int i = gt; i < tot; i += gs) {
            int j = i >> 7, k = i & 127;
            dst[k * outD + j] = s[i];
        }
    }
    if (gt < UCNT) {
        int t = P.tp[gt];
        atomicMax(&g_n2s[t], gt + 1);
        g_nneed[t] = 1;
    }
    gridsync();

    // ---- S1: edge scan ----
    for (int i = gt; i < NE; i += gs) {
        int s = P.src[i], d = P.dst[i];
        int su = g_n2s[s] - 1;
        if (su >= 0) {
            int j = atomicAdd(&g_deg[su], 1);
            if (j < MAXDEG) { g_eidx[su * MAXDEG + j] = i; g_nbr[su * MAXDEG + j] = d; }
            g_nneed[d] = 1;
        }
        int du = g_n2s[d] - 1;
        if (du >= 0 && d != s) {
            int j = atomicAdd(&g_deg[du], 1);
            if (j < MAXDEG) { g_eidx[du * MAXDEG + j] = i; g_nbr[du * MAXDEG + j] = s; }
            g_nneed[s] = 1;
        }
    }
    gridsync();

    // ---- S2: node compaction + deg clamp + pair prefix scan (block 0) ----
    for (int i = gt; i < NN; i += gs)
        if (g_nneed[i]) { int p = atomicAdd(&g_Lcnt, 1); g_Llist[p] = i; g_nodeL[i] = p; }
    if (blockIdx.x == 0) {
        if (tid < UCNT) {
            int dd = g_deg[tid];
            if (dd > MAXDEG) g_deg[tid] = MAXDEG;
        }
        __syncthreads();
        __shared__ int sCnt[UCNT];
        if (tid < UCNT) {
            int c = g_n2s[P.tp[tid]] - 1;
            sCnt[tid] = g_deg[c];
        }
        __syncthreads();
        if (tid == 0) {
            int acc = 0;
            for (int i = 0; i < UCNT; i++) {
                g_poff[i] = acc;
                acc += sCnt[i];
            }
            g_poff[UCNT] = acc;
            g_Ptot = acc;
        }
    }
    gridsync();

    // ---- S3: per-slot sort + finalize + pSlot fill, then x-GEMM ----
    for (int u = blockIdx.x; u < UCNT; u += gridDim.x) {
        int* se = (int*)sm;
        int* sn = se + MAXDEG;
        int dg = g_deg[u];
        for (int j = tid; j < dg; j += NTHR) {
            se[j] = g_eidx[u * MAXDEG + j];
            sn[j] = g_nbr[u * MAXDEG + j];
        }
        __syncthreads();
        if (tid == 0) {
            for (int i = 1; i < dg; i++) {
                int ke = se[i], kn = sn[i], j = i - 1;
                while (j >= 0 && se[j] > ke) { se[j+1] = se[j]; sn[j+1] = sn[j]; j--; }
                se[j+1] = ke; sn[j+1] = kn;
            }
            int t = P.tp[u];
            g_tgtL[u] = g_nodeL[t];
            int c = g_n2s[t];            // slot+1
            g_canon[u] = c;
            g_hasnbr[u] = (g_deg[c - 1] > 0) ? 1 : 0;
            if (c - 1 == u) g_rowSlot[g_nodeL[t]] = u + 1;
        }
        __syncthreads();
        for (int j = tid; j < dg; j += NTHR) {
            g_eidx[u * MAXDEG + j] = se[j];
            g_nbr[u * MAXDEG + j] = sn[j];
        }
        // pSlot fill: this slot's pair range
        int off = g_poff[u], cntp = g_poff[u + 1] - off;
        for (int j = tid; j < cntp; j += NTHR) g_pSlot[off + j] = u;
        __syncthreads();
    }
    {
        GJob j = { P.nf, 0, 0, P.in_b, g_xL, 1, 0, c_moff[0], g_Lcnt, 0 };
        gemm_stage(sm, j);
    }
    gridsync();

    // ---- S4: pair metadata fill + tf(l0) ----
    {
        int Pt = g_Ptot;
        for (int p = gt; p < Pt; p += gs) {
            int u = g_pSlot[p];
            int cu = g_canon[u] - 1;
            int j = p - g_poff[u];
            g_pT[p] = P.ets[g_eidx[cu * MAXDEG + j]];
            g_pNbrRow[p] = g_nodeL[g_nbr[cu * MAXDEG + j]];
        }
        GJob j = { g_xL, 0, 0, P.ftB, g_tfL, 0, 0, c_moff[1], g_Lcnt, 1 };
        gemm_stage(sm, j);
    }
    gridsync();

    for (int l = 0; l < 2; l++) {
        int base = l * 7;
        int sidb = 2 + l * 5;
        const float* bq = P.aiB + l * 384;
        // ---- E1: s = tf[nbr] + te(t)@W2t + b2 ; q = tf[tgt]@Wqt + bq ----
        {
            GJob j1 = { nullptr, P.teW1 + l*128, P.teB1 + l*128, P.teB2 + l*128,
                        g_s, 4, 1, c_moff[2 + base], g_Ptot, sidb };
            gemm_stage(sm, j1);
            GJob j2 = { g_tfL, 0, 0, bq, g_q, 2, 0, c_moff[3 + base], UCNT, sidb + 1 };
            gemm_stage(sm, j2);
        }
        gridsync();
        // ---- E2: scores = (q . (s@Wkt + bk))*scale ; E3: V = s@Wvt + bv ----
        {
            GJob j1 = { g_s, 0, 0, bq + 128, g_sc, 0, 2, c_moff[4 + base], g_Ptot, sidb + 2 };
            gemm_stage(sm, j1);
            GJob j2 = { g_s, 0, 0, bq + 256, g_V, 0, 0, c_moff[5 + base], g_Ptot, sidb + 3 };
            gemm_stage(sm, j2);
        }
        gridsync();
        // ---- fin: softmax + weighted V + attn_out + select + op ----
        fin_stage(sm, sidb + 4, g_Wt + c_moff[6 + base], P.aoB + l*128,
                  g_Wt + c_moff[7 + base], P.opB + l*128);
        gridsync();
        // ---- tf(l1) with relu(scatter) folded ----
        if (l == 0) {
            GJob j = { g_xL, g_agg, 0, P.ftB + 128, g_tfL, 3, 0, c_moff[8], g_Lcnt, 12 };
            gemm_stage(sm, j);
            gridsync();
        }
    }

    // ---- tail: fused out1/out2/lp1/lp2/lp3 per pair ----
    {
        float (*sAgg)[HH] = (float(*)[HH])sm;
        float (*sE1)[HH]  = (float(*)[HH])(sm + 256);
        float (*sEmb)[64] = (float(*)[64])(sm + 512);
        float* sZ1 = sm + 640;
        float* sZ2 = sm + 768;
        float* sRed = sm + 832;
        int nn = tid >> 7, dd = tid & 127;
        const float* o1Wt = g_Wt + c_moff[15];
        const float* o2Wt = g_Wt + c_moff[16];
        const float* l1Wt = g_Wt + c_moff[17];
        const float* l2Wt = g_Wt + c_moff[18];

        for (int p = blockIdx.x; p < 128; p += gridDim.x) {
            sAgg[nn][dd] = fmaxf(g_agg[(size_t)(2 * p + nn) * HH + dd], 0.f);
            __syncthreads();
            sE1[nn][dd] = fmaxf(matvec(sAgg[nn], o1Wt, dd, HH, HH) + P.o1B[dd], 0.f);
            __syncthreads();
            if (dd < 64)
                sEmb[nn][dd] = matvec(sE1[nn], o2Wt, dd, 64, HH) + P.o2B[dd];
            __syncthreads();
            if (tid < 128) {
                float a0 = 0.f, a1 = 0.f;
#pragma unroll 8
                for (int k = 0; k < 64; k += 2) {
                    a0 = fmaf(sEmb[0][k],     l1Wt[(k)      * HH + dd], a0);
                    a1 = fmaf(sEmb[0][k + 1], l1Wt[(k + 1)  * HH + dd], a1);
                }
#pragma unroll 8
                for (int k = 0; k < 64; k += 2) {
                    a0 = fmaf(sEmb[1][k],     l1Wt[(64 + k)     * HH + dd], a0);
                    a1 = fmaf(sEmb[1][k + 1], l1Wt[(64 + k + 1) * HH + dd], a1);
                }
                sZ1[dd] = fmaxf(a0 + a1 + P.l1B[dd], 0.f);
            }
            __syncthreads();
            if (tid < 64)
                sZ2[tid] = fmaxf(matvec(sZ1, l2Wt, tid, 64, HH) + P.l2B[tid], 0.f);
            __syncthreads();
            if (tid < 64) {
                float part = sZ2[tid] * P.l3W[tid];
                part += __shfl_xor_sync(0xffffffffu, part, 16);
                part += __shfl_xor_sync(0xffffffffu, part, 8);
                part += __shfl_xor_sync(0xffffffffu, part, 4);
                part += __shfl_xor_sync(0xffffffffu, part, 2);
                part += __shfl_xor_sync(0xffffffffu, part, 1);
                if ((tid & 31) == 0) sRed[tid >> 5] = part;
            }
            __syncthreads();
            if (tid == 0)
                out[p] = 1.f / (1.f + expf(-(sRed[0] + sRed[1] + P.l3B[0])));
            __syncthreads();
        }
    }

    // ---- cleanup for next graph replay ----
    for (int i = gt; i < NN; i += gs) g_nneed[i] = 0;
    if (gt < UCNT) {
        g_n2s[P.tp[gt]] = 0;
        g_deg[gt] = 0;
        g_rowSlot[g_tgtL[gt]] = 0;
    }
    if (gt < 16) g_tick[gt] = 0;
    if (gt == 0) g_Lcnt = 0;
}

// ---------------- launch ----------------
extern "C" void kernel_launch(void* const* d_in, const int* in_sizes, int n_in,
                              void* d_out, int out_size) {
    const float* nf   = (const float*)d_in[0];
    const int*   eidx = (const int*)d_in[1];
    const float* ets  = (const float*)d_in[2];
    const int*   tp   = (const int*)d_in[3];
    const float* in_W = (const float*)d_in[4];
    const float* in_b = (const float*)d_in[5];
    const float* teW1 = (const float*)d_in[6];
    const float* teB1 = (const float*)d_in[7];
    const float* teW2 = (const float*)d_in[8];
    const float* teB2 = (const float*)d_in[9];
    const float* aiW  = (const float*)d_in[10];
    const float* aiB  = (const float*)d_in[11];
    const float* aoW  = (const float*)d_in[12];
    const float* aoB  = (const float*)d_in[13];
    const float* ftW  = (const float*)d_in[14];
    const float* ftB  = (const float*)d_in[15];
    const float* opW  = (const float*)d_in[16];
    const float* opB  = (const float*)d_in[17];
    const float* o1W  = (const float*)d_in[18];
    const float* o1B  = (const float*)d_in[19];
    const float* o2W  = (const float*)d_in[20];
    const float* o2B  = (const float*)d_in[21];
    const float* l1W  = (const float*)d_in[22];
    const float* l1B  = (const float*)d_in[23];
    const float* l2W  = (const float*)d_in[24];
    const float* l2B  = (const float*)d_in[25];
    const float* l3W  = (const float*)d_in[26];
    const float* l3B  = (const float*)d_in[27];
    float* out = (float*)d_out;

    Params P;
    P.wsrc[0] = in_W;
    for (int l = 0; l < 2; l++) {
        P.wsrc[1 + 7*l] = ftW + l * 16384;
        P.wsrc[2 + 7*l] = teW2 + l * 16384;
        P.wsrc[3 + 7*l] = aiW + l * 384 * 128;            // Wq
        P.wsrc[4 + 7*l] = aiW + l * 384 * 128 + 16384;    // Wk
        P.wsrc[5 + 7*l] = aiW + l * 384 * 128 + 32768;    // Wv
        P.wsrc[6 + 7*l] = aoW + l * 16384;
        P.wsrc[7 + 7*l] = opW + l * 16384;
    }
    P.wsrc[15] = o1W; P.wsrc[16] = o2W; P.wsrc[17] = l1W; P.wsrc[18] = l2W;
    P.tp = tp; P.src = eidx; P.dst = eidx + NE;
    P.ets = ets; P.nf = nf;
    P.in_b = in_b; P.teW1 = teW1; P.teB1 = teB1; P.teB2 = teB2;
    P.aiB = aiB; P.aoB = aoB; P.ftB = ftB; P.opB = opB;
    P.o1B = o1B; P.o2B = o2B; P.l1B = l1B; P.l2B = l2B;
    P.l3W = l3W; P.l3B = l3B;

    cudaFuncSetAttribute(k_mega, cudaFuncAttributeMaxDynamicSharedMemorySize, SMEM_SZ);

    int nSM = 148;
    cudaDeviceGetAttribute(&nSM, cudaDevAttrMultiProcessorCount, 0);
    int occ = 1;
    cudaOccupancyMaxActiveBlocksPerMultiprocessor(&occ, k_mega, NTHR, SMEM_SZ);
    int nb = nSM * occ;
    if (nb > 296) nb = 296;
    if (nb < 8) nb = 8;

    k_mega<<<nb, NTHR, SMEM_SZ>>>(P, out);
}